// round 4
// baseline (speedup 1.0000x reference)
#include <cuda_runtime.h>
#include <cuda_bf16.h>
#include <math.h>
#include <stdint.h>

#define NROWS 200000
#define DIN   512
#define DOUT  128
#define NQKV  384
#define BK    32                              // k per chunk (IMMA k32)
#define NCHUNKS (DIN / BK)                    // 16
#define MTILE 128
#define NBLK_M ((NROWS + MTILE - 1) / MTILE)  // 1563

#define CHUNK 512
#define NB    ((NROWS + CHUNK - 1) / CHUNK)   // 391

// quantization: x = S*(128*q1 + q2), q in s8, |x'| <= 16256
#define QMAXF   16256.0f
#define BOUND_H 6.5f
#define BOUND_W 0.1370f
#define QS_H    (QMAXF / BOUND_H)
#define QS_W    (QMAXF / BOUND_W)
#define FSCALE  ((float)(((double)BOUND_H * (double)BOUND_W * 128.0) / \
                         ((double)QMAXF * (double)QMAXF)))

// ---- scratch (device globals; no runtime allocation) ----
__device__ float g_Q[(size_t)NROWS * DOUT];
__device__ float g_K[(size_t)NROWS * DOUT];
__device__ float g_V[(size_t)NROWS * DOUT];
__device__ float g_KVpart[(size_t)NB * DOUT * DOUT];
__device__ float g_kspart[(size_t)NB * DOUT];
__device__ float g_KV[DOUT * DOUT];
__device__ float g_ksum[DOUT];

// int8 weights: [part(hi/lo)][n=384][k=512]
__device__ int8_t g_Wi8[2 * NQKV * DIN];

// ---- qkv smem layout ----
// A: [stage][part][128 rows x 48B]  (32B data + 16B pad; 12r mod 32 perm -> conflict-free ldsm)
// B: [stage][part][128 n-rows x 48B]
#define ROW_B     48
#define PART_B    (128 * ROW_B)       // 6144
#define STAGE_B   (2 * PART_B)        // 12288
#define SM_B_OFF  (2 * STAGE_B)       // 24576
#define SM_QKV_TOTAL (SM_B_OFF + 2 * STAGE_B)  // 49152

static __device__ __forceinline__ uint32_t smem_u32(const void* p) {
    uint32_t a;
    asm("{ .reg .u64 t; cvta.to.shared.u64 t, %1; cvt.u32.u64 %0, t; }" : "=r"(a) : "l"(p));
    return a;
}
static __device__ __forceinline__ void cp16(uint32_t dst, const void* src) {
    asm volatile("cp.async.cg.shared.global [%0], [%1], 16;" :: "r"(dst), "l"(src) : "memory");
}
#define CP_COMMIT()  asm volatile("cp.async.commit_group;" ::: "memory")
#define CP_WAIT(N)   asm volatile("cp.async.wait_group %0;" :: "n"(N) : "memory")

static __device__ __forceinline__ void ldsm_x4(uint32_t* r, uint32_t addr) {
    asm volatile("ldmatrix.sync.aligned.m8n8.x4.shared.b16 {%0,%1,%2,%3}, [%4];"
                 : "=r"(r[0]), "=r"(r[1]), "=r"(r[2]), "=r"(r[3]) : "r"(addr));
}
static __device__ __forceinline__ void imma16832(int* d, const uint32_t* a,
                                                 const uint32_t* b) {
    asm volatile(
        "mma.sync.aligned.m16n8k32.row.col.s32.s8.s8.s32 "
        "{%0,%1,%2,%3}, {%4,%5,%6,%7}, {%8,%9}, {%0,%1,%2,%3};"
        : "+r"(d[0]), "+r"(d[1]), "+r"(d[2]), "+r"(d[3])
        : "r"(a[0]), "r"(a[1]), "r"(a[2]), "r"(a[3]), "r"(b[0]), "r"(b[1]));
}

__device__ __forceinline__ float elu_p1(float x) {
    return x > 0.0f ? x + 1.0f : expf(x);
}

static __device__ __forceinline__ void quant2(float x, float qs, int& q1, int& q2) {
    float xp = x * qs;
    xp = fminf(fmaxf(xp, -QMAXF), QMAXF);
    float f1 = rintf(xp * (1.0f / 128.0f));
    f1 = fminf(fmaxf(f1, -127.0f), 127.0f);
    float f2 = rintf(xp - 128.0f * f1);
    f2 = fminf(fmaxf(f2, -127.0f), 127.0f);
    q1 = (int)f1;
    q2 = (int)f2;
}
static __device__ __forceinline__ uint32_t pack4(int a, int b, int c, int d) {
    return (uint32_t)(a & 0xff) | ((uint32_t)(b & 0xff) << 8) |
           ((uint32_t)(c & 0xff) << 16) | ((uint32_t)(d & 0xff) << 24);
}

// ============================================================================
// Kernel W: quantize weights into 2-term int8, layout [part][n=384][k=512].
// ============================================================================
__global__ void convert_w(const float* __restrict__ Wq,
                          const float* __restrict__ Wk,
                          const float* __restrict__ Wv)
{
    int idx = blockIdx.x * 256 + threadIdx.x;      // over 384*512
    if (idx >= NQKV * DIN) return;
    int n = idx / DIN;
    int k = idx % DIN;
    const float* W = (n < 128) ? Wq : (n < 256) ? Wk : Wv;
    float x = W[(size_t)k * DOUT + (n & 127)];
    int q1, q2;
    quant2(x, QS_W, q1, q2);
    g_Wi8[(size_t)n * DIN + k]                     = (int8_t)q1;
    g_Wi8[(size_t)(NQKV + n) * DIN + k]            = (int8_t)q2;
}

// ============================================================================
// Kernel A: [Q|K|V] = f(h @ W_which) via IMMA s8 2-term (3-pass) split.
// Grid (3, 1563). Block 512 threads = 16 warps (4x4 of 32x32 warp tiles).
// ============================================================================
__global__ __launch_bounds__(512, 1) void qkv_imma(const float* __restrict__ h)
{
    extern __shared__ __align__(256) unsigned char sm[];
    const uint32_t sbase = smem_u32(sm);

    const int which = blockIdx.x;
    const int row0  = blockIdx.y * MTILE;
    const int tid   = threadIdx.x;
    const int wid   = tid >> 5;
    const int lane  = tid & 31;

    const int wm = wid & 3;
    const int wn = wid >> 2;
    const int m0 = wm * 32;
    const int n0 = wn * 32;

    // A convert mapping: row = tid>>2, seg = (tid&3)*8 (floats within k32)
    const int arow = tid >> 2;
    const int aseg = (tid & 3) * 8;
    int lrow = row0 + arow;
    if (lrow >= NROWS) lrow = NROWS - 1;
    const float* hrow = h + (size_t)lrow * DIN + aseg;
    const uint32_t a_sts = (uint32_t)(arow * ROW_B + aseg);   // 1 byte per element

    // B cp.async mapping: part = tid>>8, row = (tid&255)>>1, half = tid&1
    const int b_part = tid >> 8;
    const int b_row  = (tid & 255) >> 1;
    const int b_half = tid & 1;
    const int8_t* b_src_base = g_Wi8 + (size_t)(b_part * NQKV + which * 128 + b_row) * DIN
                                     + b_half * 16;
    const uint32_t b_dst_base = sbase + SM_B_OFF + b_part * PART_B +
                                b_row * ROW_B + b_half * 16;

    // ldmatrix per-lane offsets
    const int ag = lane >> 3;
    const uint32_t a_lane_off = (uint32_t)((((ag & 1) * 8) + (lane & 7)) * ROW_B +
                                           ((ag >> 1) * 16));
    const uint32_t b_lane_off = (uint32_t)((((ag >> 1) * 8) + (lane & 7)) * ROW_B +
                                           ((ag & 1) * 16));

    int acc_hh[2][4][4];
    int acc_x [2][4][4];
    #pragma unroll
    for (int i = 0; i < 2; i++)
        #pragma unroll
        for (int j = 0; j < 4; j++)
            #pragma unroll
            for (int r = 0; r < 4; r++) { acc_hh[i][j][r] = 0; acc_x[i][j][r] = 0; }

    auto sts_A = [&](int stage, const float* f) {
        int q1[8], q2[8];
        #pragma unroll
        for (int i = 0; i < 8; i++) quant2(f[i], QS_H, q1[i], q2[i]);
        uint32_t h0 = pack4(q1[0], q1[1], q1[2], q1[3]);
        uint32_t h1 = pack4(q1[4], q1[5], q1[6], q1[7]);
        uint32_t l0 = pack4(q2[0], q2[1], q2[2], q2[3]);
        uint32_t l1 = pack4(q2[4], q2[5], q2[6], q2[7]);
        uint32_t dhi = sbase + stage * STAGE_B + a_sts;
        uint32_t dlo = dhi + PART_B;
        asm volatile("st.shared.v2.b32 [%0], {%1,%2};" :: "r"(dhi), "r"(h0), "r"(h1));
        asm volatile("st.shared.v2.b32 [%0], {%1,%2};" :: "r"(dlo), "r"(l0), "r"(l1));
    };
    auto issue_B = [&](int c, int stage) {
        cp16(b_dst_base + stage * STAGE_B, b_src_base + c * BK);
        CP_COMMIT();
    };

    // ---- prologue ----
    float f[8];
    {
        float4 u = *(const float4*)(hrow);
        float4 w = *(const float4*)(hrow + 4);
        f[0]=u.x; f[1]=u.y; f[2]=u.z; f[3]=u.w; f[4]=w.x; f[5]=w.y; f[6]=w.z; f[7]=w.w;
    }
    issue_B(0, 0);
    sts_A(0, f);

    for (int c = 0; c < NCHUNKS; c++) {
        const int stage = c & 1;

        if (c + 1 < NCHUNKS) {
            float4 u = *(const float4*)(hrow + (c + 1) * BK);
            float4 w = *(const float4*)(hrow + (c + 1) * BK + 4);
            f[0]=u.x; f[1]=u.y; f[2]=u.z; f[3]=u.w; f[4]=w.x; f[5]=w.y; f[6]=w.z; f[7]=w.w;
            issue_B(c + 1, stage ^ 1);
            CP_WAIT(1);
        } else {
            CP_WAIT(0);
        }
        __syncthreads();   // B(c) arrived, A(c) visible

        const uint32_t Ab = sbase + stage * STAGE_B;
        const uint32_t Bb = sbase + SM_B_OFF + stage * STAGE_B;

        uint32_t afr[2][2][4];   // [part][im]
        #pragma unroll
        for (int p = 0; p < 2; p++)
            #pragma unroll
            for (int im = 0; im < 2; im++)
                ldsm_x4(afr[p][im],
                        Ab + p * PART_B + (uint32_t)((m0 + im * 16) * ROW_B) + a_lane_off);

        #pragma unroll
        for (int jp = 0; jp < 2; jp++) {
            uint32_t bhi[4], blo[4];
            ldsm_x4(bhi, Bb + 0 * PART_B + (uint32_t)((n0 + jp * 16) * ROW_B) + b_lane_off);
            ldsm_x4(blo, Bb + 1 * PART_B + (uint32_t)((n0 + jp * 16) * ROW_B) + b_lane_off);
            #pragma unroll
            for (int jh = 0; jh < 2; jh++) {
                const int j = jp * 2 + jh;
                #pragma unroll
                for (int im = 0; im < 2; im++) {
                    imma16832(acc_hh[im][j], afr[0][im], &bhi[jh * 2]);  // hi*hi
                    imma16832(acc_x [im][j], afr[0][im], &blo[jh * 2]);  // hi*lo
                    imma16832(acc_x [im][j], afr[1][im], &bhi[jh * 2]);  // lo*hi
                }
            }
        }

        if (c + 1 < NCHUNKS) sts_A(stage ^ 1, f);
    }

    // ---- epilogue ----
    float* Out = (which == 0) ? g_Q : (which == 1) ? g_K : g_V;
    const bool act = (which < 2);
    const int g = lane >> 2;
    const int t = lane & 3;

    #pragma unroll
    for (int im = 0; im < 2; im++) {
        const int r0 = row0 + m0 + im * 16 + g;
        const int r1 = r0 + 8;
        #pragma unroll
        for (int j = 0; j < 4; j++) {
            const int col = n0 + j * 8 + t * 2;
            float c0 = FSCALE * (float)((acc_hh[im][j][0] << 7) + acc_x[im][j][0]);
            float c1 = FSCALE * (float)((acc_hh[im][j][1] << 7) + acc_x[im][j][1]);
            float c2 = FSCALE * (float)((acc_hh[im][j][2] << 7) + acc_x[im][j][2]);
            float c3 = FSCALE * (float)((acc_hh[im][j][3] << 7) + acc_x[im][j][3]);
            if (act) {
                c0 = elu_p1(c0); c1 = elu_p1(c1);
                c2 = elu_p1(c2); c3 = elu_p1(c3);
            }
            if (r0 < NROWS) *(float2*)(Out + (size_t)r0 * DOUT + col) = make_float2(c0, c1);
            if (r1 < NROWS) *(float2*)(Out + (size_t)r1 * DOUT + col) = make_float2(c2, c3);
        }
    }
}

// ============================================================================
// Kernel B: per-block partial KV = K_chunk^T @ V_chunk, plus partial k_sum.
// ============================================================================
__global__ __launch_bounds__(256) void kv_kernel()
{
    __shared__ float Ks[16][128];
    __shared__ float Vs[16][128];

    const int tid = threadIdx.x;
    const int cg  = tid & 15;
    const int rg  = tid >> 4;
    const int mc  = cg * 8;
    const int mr  = rg * 8;

    float acc[8][8];
    #pragma unroll
    for (int i = 0; i < 8; i++)
        #pragma unroll
        for (int j = 0; j < 8; j++) acc[i][j] = 0.0f;
    float ksum_local = 0.0f;

    const int base = blockIdx.x * CHUNK;
    const int kr0 = tid >> 5;
    const int cq  = (tid & 31) * 4;
    const int kr1 = (tid + 256) >> 5;

    for (int t = 0; t < CHUNK; t += 16) {
        const int ra = base + t + kr0;
        const int rb = base + t + kr1;
        float4 k0 = make_float4(0, 0, 0, 0), k1 = k0, v0 = k0, v1 = k0;
        if (ra < NROWS) {
            k0 = *(const float4*)(g_K + (size_t)ra * DOUT + cq);
            v0 = *(const float4*)(g_V + (size_t)ra * DOUT + cq);
        }
        if (rb < NROWS) {
            k1 = *(const float4*)(g_K + (size_t)rb * DOUT + cq);
            v1 = *(const float4*)(g_V + (size_t)rb * DOUT + cq);
        }
        __syncthreads();
        *(float4*)&Ks[kr0][cq] = k0;
        *(float4*)&Ks[kr1][cq] = k1;
        *(float4*)&Vs[kr0][cq] = v0;
        *(float4*)&Vs[kr1][cq] = v1;
        __syncthreads();

        #pragma unroll
        for (int kk = 0; kk < 16; kk++) {
            float4 ka0 = *(const float4*)&Ks[kk][mr];
            float4 ka1 = *(const float4*)&Ks[kk][mr + 4];
            float4 vb0 = *(const float4*)&Vs[kk][mc];
            float4 vb1 = *(const float4*)&Vs[kk][mc + 4];
            float kr[8] = {ka0.x, ka0.y, ka0.z, ka0.w, ka1.x, ka1.y, ka1.z, ka1.w};
            float vr[8] = {vb0.x, vb0.y, vb0.z, vb0.w, vb1.x, vb1.y, vb1.z, vb1.w};
            #pragma unroll
            for (int i = 0; i < 8; i++)
                #pragma unroll
                for (int j = 0; j < 8; j++)
                    acc[i][j] = fmaf(kr[i], vr[j], acc[i][j]);
        }

        if (tid < DOUT) {
            #pragma unroll
            for (int kk = 0; kk < 16; kk++)
                ksum_local += Ks[kk][tid];
        }
    }

    float* kvout = g_KVpart + (size_t)blockIdx.x * (DOUT * DOUT);
    #pragma unroll
    for (int i = 0; i < 8; i++) {
        float* row = kvout + (size_t)(mr + i) * DOUT + mc;
        *(float4*)(row)     = make_float4(acc[i][0], acc[i][1], acc[i][2], acc[i][3]);
        *(float4*)(row + 4) = make_float4(acc[i][4], acc[i][5], acc[i][6], acc[i][7]);
    }
    if (tid < DOUT)
        g_kspart[(size_t)blockIdx.x * DOUT + tid] = ksum_local;
}

// ============================================================================
// Reduce partials -> g_KV, g_ksum.
// ============================================================================
__global__ void reduce_kernel()
{
    const int i = blockIdx.x * blockDim.x + threadIdx.x;
    if (i < DOUT * DOUT) {
        float s = 0.0f;
        for (int b = 0; b < NB; b++)
            s += g_KVpart[(size_t)b * (DOUT * DOUT) + i];
        g_KV[i] = s;
    } else {
        const int j = i - DOUT * DOUT;
        if (j < DOUT) {
            float s = 0.0f;
            for (int b = 0; b < NB; b++)
                s += g_kspart[(size_t)b * DOUT + j];
            g_ksum[j] = s;
        }
    }
}

// ============================================================================
// Kernel C: out = elu((Q @ KV) * (1 / (Q @ ksum)))
// ============================================================================
#define SMEMC_FLOATS (DOUT * DOUT + DOUT * 68 + DOUT + 64)

__global__ __launch_bounds__(256) void out_kernel(float* __restrict__ out)
{
    extern __shared__ float smf[];
    float* KVs    = smf;
    float* Qs     = smf + DOUT * DOUT;
    float* ksum_s = Qs + DOUT * 68;
    float* z_s    = ksum_s + DOUT;

    const int tid  = threadIdx.x;
    const int row0 = blockIdx.x * 64;

    for (int i = tid; i < (DOUT * DOUT) / 4; i += 256)
        ((float4*)KVs)[i] = ((const float4*)g_KV)[i];
    if (tid < DOUT)
        ksum_s[tid] = g_ksum[tid];

    for (int i = tid; i < 2048; i += 256) {
        const int r  = i >> 5;
        const int cq = (i & 31) * 4;
        float4 q = *(const float4*)(g_Q + (size_t)(row0 + r) * DOUT + cq);
        Qs[(cq + 0) * 68 + r] = q.x;
        Qs[(cq + 1) * 68 + r] = q.y;
        Qs[(cq + 2) * 68 + r] = q.z;
        Qs[(cq + 3) * 68 + r] = q.w;
    }
    __syncthreads();

    if (tid < 64) {
        float dot = 0.0f;
        #pragma unroll 8
        for (int k = 0; k < DOUT; k++)
            dot = fmaf(Qs[k * 68 + tid], ksum_s[k], dot);
        z_s[tid] = 1.0f / dot;
    }
    __syncthreads();

    const int cg = tid & 15;
    const int rg = tid >> 4;
    const int mc = cg * 8;
    const int mr = rg * 4;

    float acc[4][8];
    #pragma unroll
    for (int i = 0; i < 4; i++)
        #pragma unroll
        for (int j = 0; j < 8; j++) acc[i][j] = 0.0f;

    #pragma unroll 8
    for (int kk = 0; kk < DOUT; kk++) {
        float4 a  = *(const float4*)&Qs[kk * 68 + mr];
        float4 b0 = *(const float4*)&KVs[kk * DOUT + mc];
        float4 b1 = *(const float4*)&KVs[kk * DOUT + mc + 4];
        float ar[4] = {a.x, a.y, a.z, a.w};
        float br[8] = {b0.x, b0.y, b0.z, b0.w, b1.x, b1.y, b1.z, b1.w};
        #pragma unroll
        for (int i = 0; i < 4; i++)
            #pragma unroll
            for (int j = 0; j < 8; j++)
                acc[i][j] = fmaf(ar[i], br[j], acc[i][j]);
    }

    #pragma unroll
    for (int i = 0; i < 4; i++) {
        const float z = z_s[mr + i];
        float v[8];
        #pragma unroll
        for (int j = 0; j < 8; j++) {
            float x = acc[i][j] * z;
            v[j] = x > 0.0f ? x : expm1f(x);
        }
        float* orow = out + (size_t)(row0 + mr + i) * DOUT + mc;
        *(float4*)(orow)     = make_float4(v[0], v[1], v[2], v[3]);
        *(float4*)(orow + 4) = make_float4(v[4], v[5], v[6], v[7]);
    }
}

// ============================================================================
// Launch
// ============================================================================
extern "C" void kernel_launch(void* const* d_in, const int* in_sizes, int n_in,
                              void* d_out, int out_size)
{
    const float* h  = (const float*)d_in[0];
    const float* Wq = (const float*)d_in[1];
    const float* Wk = (const float*)d_in[2];
    const float* Wv = (const float*)d_in[3];
    float* out = (float*)d_out;

    cudaFuncSetAttribute(qkv_imma, cudaFuncAttributeMaxDynamicSharedMemorySize, SM_QKV_TOTAL);
    const int smemC = SMEMC_FLOATS * (int)sizeof(float);
    cudaFuncSetAttribute(out_kernel, cudaFuncAttributeMaxDynamicSharedMemorySize, smemC);

    convert_w<<<(NQKV * DIN + 255) / 256, 256>>>(Wq, Wk, Wv);

    dim3 gridA(3, NBLK_M);
    qkv_imma<<<gridA, 512, SM_QKV_TOTAL>>>(h);

    kv_kernel<<<NB, 256>>>();
    reduce_kernel<<<(DOUT * DOUT + DOUT + 255) / 256, 256>>>();
    out_kernel<<<NROWS / 64, 256, smemC>>>(out);
}

// round 5
// speedup vs baseline: 2.3894x; 2.3894x over previous
#include <cuda_runtime.h>
#include <cuda_fp16.h>
#include <math.h>
#include <stdint.h>

#define NROWS 200000
#define DIN   512
#define DOUT  128
#define NQKV  384
#define BK    32
#define NCHUNKS (DIN / BK)                    // 16
#define MTILE 128
#define NBLK_M ((NROWS + MTILE - 1) / MTILE)  // 1563

#define CHUNK 512
#define NB    ((NROWS + CHUNK - 1) / CHUNK)   // 391

// ---- scratch (device globals; no runtime allocation) ----
__device__ __half g_Q[(size_t)NROWS * DOUT];
__device__ __half g_K[(size_t)NROWS * DOUT];
__device__ __half g_V[(size_t)NROWS * DOUT];
__device__ float g_KVpart[(size_t)NB * DOUT * DOUT];
__device__ float g_kspart[(size_t)NB * DOUT];
__device__ float g_KV[DOUT * DOUT];
__device__ float g_ksum[DOUT];

// fp16 weights, row-major [k][384] (n = which*128 + col)
__device__ __half g_Wh[(size_t)DIN * NQKV];

// ---- qkv smem layout (single fp16 part, double buffered) ----
// A: [stage][128 rows x 80B]   (BK=32 fp16 = 64B data + 16B pad)
// B: [stage][32 k-rows x 272B] (128 fp16 = 256B data + 16B pad)
#define A_ROW_B   80
#define A_STAGE_B (MTILE * A_ROW_B)        // 10240
#define B_ROW_B   272
#define B_STAGE_B (BK * B_ROW_B)           // 8704
#define SM_B_OFF  (2 * A_STAGE_B)          // 20480
#define SM_QKV_TOTAL (SM_B_OFF + 2 * B_STAGE_B)  // 37888

static __device__ __forceinline__ uint32_t smem_u32(const void* p) {
    uint32_t a;
    asm("{ .reg .u64 t; cvta.to.shared.u64 t, %1; cvt.u32.u64 %0, t; }" : "=r"(a) : "l"(p));
    return a;
}
static __device__ __forceinline__ void cp16(uint32_t dst, const void* src) {
    asm volatile("cp.async.cg.shared.global [%0], [%1], 16;" :: "r"(dst), "l"(src) : "memory");
}
#define CP_COMMIT()  asm volatile("cp.async.commit_group;" ::: "memory")
#define CP_WAIT(N)   asm volatile("cp.async.wait_group %0;" :: "n"(N) : "memory")

static __device__ __forceinline__ void ldsm_x4(uint32_t* r, uint32_t addr) {
    asm volatile("ldmatrix.sync.aligned.m8n8.x4.shared.b16 {%0,%1,%2,%3}, [%4];"
                 : "=r"(r[0]), "=r"(r[1]), "=r"(r[2]), "=r"(r[3]) : "r"(addr));
}
static __device__ __forceinline__ void ldsm_x4_t(uint32_t* r, uint32_t addr) {
    asm volatile("ldmatrix.sync.aligned.m8n8.x4.trans.shared.b16 {%0,%1,%2,%3}, [%4];"
                 : "=r"(r[0]), "=r"(r[1]), "=r"(r[2]), "=r"(r[3]) : "r"(addr));
}
static __device__ __forceinline__ void mma16816h(float* d, const uint32_t* a,
                                                 const uint32_t* b) {
    asm volatile(
        "mma.sync.aligned.m16n8k16.row.col.f32.f16.f16.f32 "
        "{%0,%1,%2,%3}, {%4,%5,%6,%7}, {%8,%9}, {%0,%1,%2,%3};"
        : "+f"(d[0]), "+f"(d[1]), "+f"(d[2]), "+f"(d[3])
        : "r"(a[0]), "r"(a[1]), "r"(a[2]), "r"(a[3]), "r"(b[0]), "r"(b[1]));
}

__device__ __forceinline__ float elu_p1(float x) {
    return x > 0.0f ? x + 1.0f : expf(x);
}

// ============================================================================
// Kernel W: fp16 weight conversion into [k][384].
// ============================================================================
__global__ void convert_w(const float* __restrict__ Wq,
                          const float* __restrict__ Wk,
                          const float* __restrict__ Wv)
{
    int idx = blockIdx.x * 256 + threadIdx.x;     // 512*384
    if (idx >= DIN * NQKV) return;
    int k = idx / NQKV;
    int n = idx % NQKV;
    const float* W = (n < 128) ? Wq : (n < 256) ? Wk : Wv;
    g_Wh[idx] = __float2half_rn(W[(size_t)k * DOUT + (n & 127)]);
}

// ============================================================================
// Kernel A: [Q|K|V] = f(h @ W_which) via single-pass fp16 mma.sync.
// Grid (3, 1563): which fastest -> L2 reuse of h tile.
// Block 128x128, 8 warps (4x2), warp tile 32x64, BK=32 double-buffered.
// ============================================================================
__global__ __launch_bounds__(256, 1) void qkv_mma(const float* __restrict__ h)
{
    extern __shared__ __align__(256) unsigned char sm[];
    const uint32_t sbase = smem_u32(sm);

    const int which = blockIdx.x;
    const int row0  = blockIdx.y * MTILE;
    const int tid   = threadIdx.x;
    const int wid   = tid >> 5;
    const int lane  = tid & 31;

    const int wm = wid & 3;
    const int wn = wid >> 2;
    const int m0 = wm * 32;
    const int n0w = wn * 64;

    // A load/convert: row = tid>>1, seg = (tid&1)*16 floats
    const int arow = tid >> 1;
    const int aseg = (tid & 1) * 16;
    int lrow = row0 + arow;
    if (lrow >= NROWS) lrow = NROWS - 1;
    const float* hrow = h + (size_t)lrow * DIN + aseg;
    const uint32_t a_sts_off = (uint32_t)(arow * A_ROW_B + aseg * 2);

    const int nbase = which * 128;

    float acc[2][8][4];
    #pragma unroll
    for (int i = 0; i < 2; i++)
        #pragma unroll
        for (int j = 0; j < 8; j++)
            #pragma unroll
            for (int r = 0; r < 4; r++) acc[i][j][r] = 0.0f;

    const int a_r = (lane & 7) + (lane & 8);
    const int a_c = ((lane >> 4) & 1) * 8;
    const int b_k = (lane & 7) + (lane & 8);
    const int b_n = ((lane >> 4) & 1) * 8;

    auto issue_B = [&](int c, int stage) {
        // 512 cp16 per chunk (32 rows x 16), 2 per thread
        const size_t src_row0 = (size_t)(c * BK) * NQKV + nbase;
        uint32_t dstb = sbase + SM_B_OFF + stage * B_STAGE_B;
        #pragma unroll
        for (int it = 0; it < 2; it++) {
            int idx = tid + it * 256;
            int r = idx >> 4, c16 = idx & 15;
            cp16(dstb + r * B_ROW_B + c16 * 16,
                 g_Wh + src_row0 + (size_t)r * NQKV + c16 * 8);
        }
        CP_COMMIT();
    };
    auto sts_A = [&](int stage, const float4* v) {
        uint32_t hx[8];
        #pragma unroll
        for (int j = 0; j < 4; j++) {
            __half2 p0 = __floats2half2_rn(v[j].x, v[j].y);
            __half2 p1 = __floats2half2_rn(v[j].z, v[j].w);
            hx[2*j]   = *(uint32_t*)&p0;
            hx[2*j+1] = *(uint32_t*)&p1;
        }
        uint32_t dst = sbase + stage * A_STAGE_B + a_sts_off;
        asm volatile("st.shared.v4.b32 [%0], {%1,%2,%3,%4};" :: "r"(dst),
                     "r"(hx[0]),"r"(hx[1]),"r"(hx[2]),"r"(hx[3]));
        asm volatile("st.shared.v4.b32 [%0], {%1,%2,%3,%4};" :: "r"(dst+16),
                     "r"(hx[4]),"r"(hx[5]),"r"(hx[6]),"r"(hx[7]));
    };

    // ---- prologue ----
    float4 v[4];
    #pragma unroll
    for (int j = 0; j < 4; j++) v[j] = *(const float4*)(hrow + 4 * j);
    issue_B(0, 0);
    sts_A(0, v);

    for (int c = 0; c < NCHUNKS; c++) {
        const int stage = c & 1;

        if (c + 1 < NCHUNKS) {
            #pragma unroll
            for (int j = 0; j < 4; j++)
                v[j] = *(const float4*)(hrow + (c + 1) * BK + 4 * j);
            issue_B(c + 1, stage ^ 1);
            CP_WAIT(1);
        } else {
            CP_WAIT(0);
        }
        __syncthreads();   // B(c) arrived, A(c) STS visible

        const uint32_t Ab = sbase + stage * A_STAGE_B;
        const uint32_t Bb = sbase + SM_B_OFF + stage * B_STAGE_B;
        #pragma unroll
        for (int ks = 0; ks < 2; ks++) {
            const int k0 = ks * 16;
            uint32_t afr[2][4];
            #pragma unroll
            for (int im = 0; im < 2; im++)
                ldsm_x4(afr[im], Ab + (uint32_t)((m0 + im * 16 + a_r) * A_ROW_B +
                                                 (k0 + a_c) * 2));
            uint32_t bfr[4][4];
            #pragma unroll
            for (int jn = 0; jn < 4; jn++)
                ldsm_x4_t(bfr[jn], Bb + (uint32_t)((k0 + b_k) * B_ROW_B +
                                                   (n0w + jn * 16 + b_n) * 2));
            #pragma unroll
            for (int im = 0; im < 2; im++)
                #pragma unroll
                for (int jn = 0; jn < 4; jn++) {
                    mma16816h(acc[im][jn * 2 + 0], afr[im], &bfr[jn][0]);
                    mma16816h(acc[im][jn * 2 + 1], afr[im], &bfr[jn][2]);
                }
        }

        if (c + 1 < NCHUNKS) sts_A(stage ^ 1, v);
    }

    // ---- epilogue: fp16 stores ----
    __half* Out = (which == 0) ? g_Q : (which == 1) ? g_K : g_V;
    const bool act = (which < 2);
    const int g = lane >> 2;
    const int t = lane & 3;

    #pragma unroll
    for (int im = 0; im < 2; im++) {
        const int r0 = row0 + m0 + im * 16 + g;
        const int r1 = r0 + 8;
        #pragma unroll
        for (int j = 0; j < 8; j++) {
            const int col = n0w + j * 8 + t * 2;
            float c0 = acc[im][j][0], c1 = acc[im][j][1];
            float c2 = acc[im][j][2], c3 = acc[im][j][3];
            if (act) {
                c0 = elu_p1(c0); c1 = elu_p1(c1);
                c2 = elu_p1(c2); c3 = elu_p1(c3);
            }
            if (r0 < NROWS)
                *(__half2*)(Out + (size_t)r0 * DOUT + col) = __floats2half2_rn(c0, c1);
            if (r1 < NROWS)
                *(__half2*)(Out + (size_t)r1 * DOUT + col) = __floats2half2_rn(c2, c3);
        }
    }
}

// ============================================================================
// Kernel B: per-block partial KV = K_chunk^T @ V_chunk, plus partial k_sum.
// K/V loaded as fp16, converted, fp32 FMA compute (known good).
// ============================================================================
__global__ __launch_bounds__(256) void kv_kernel()
{
    __shared__ float Ks[16][128];
    __shared__ float Vs[16][128];

    const int tid = threadIdx.x;
    const int cg  = tid & 15;
    const int rg  = tid >> 4;
    const int mc  = cg * 8;
    const int mr  = rg * 8;

    float acc[8][8];
    #pragma unroll
    for (int i = 0; i < 8; i++)
        #pragma unroll
        for (int j = 0; j < 8; j++) acc[i][j] = 0.0f;
    float ksum_local = 0.0f;

    const int base = blockIdx.x * CHUNK;
    const int kr  = tid >> 4;            // 0..15 (row within 16-row slab)
    const int cq8 = (tid & 15) * 8;      // 8 halves per thread

    for (int t = 0; t < CHUNK; t += 16) {
        const int row = base + t + kr;
        uint4 kraw = make_uint4(0, 0, 0, 0), vraw = kraw;
        if (row < NROWS) {
            kraw = *(const uint4*)(g_K + (size_t)row * DOUT + cq8);
            vraw = *(const uint4*)(g_V + (size_t)row * DOUT + cq8);
        }
        __syncthreads();
        {
            const uint32_t* kw = &kraw.x;
            const uint32_t* vw = &vraw.x;
            #pragma unroll
            for (int q = 0; q < 4; q++) {
                float2 kf = __half22float2(*(const __half2*)&kw[q]);
                float2 vf = __half22float2(*(const __half2*)&vw[q]);
                Ks[kr][cq8 + 2*q]     = kf.x;
                Ks[kr][cq8 + 2*q + 1] = kf.y;
                Vs[kr][cq8 + 2*q]     = vf.x;
                Vs[kr][cq8 + 2*q + 1] = vf.y;
            }
        }
        __syncthreads();

        #pragma unroll
        for (int kk = 0; kk < 16; kk++) {
            float4 ka0 = *(const float4*)&Ks[kk][mr];
            float4 ka1 = *(const float4*)&Ks[kk][mr + 4];
            float4 vb0 = *(const float4*)&Vs[kk][mc];
            float4 vb1 = *(const float4*)&Vs[kk][mc + 4];
            float kr8[8] = {ka0.x, ka0.y, ka0.z, ka0.w, ka1.x, ka1.y, ka1.z, ka1.w};
            float vr8[8] = {vb0.x, vb0.y, vb0.z, vb0.w, vb1.x, vb1.y, vb1.z, vb1.w};
            #pragma unroll
            for (int i = 0; i < 8; i++)
                #pragma unroll
                for (int j = 0; j < 8; j++)
                    acc[i][j] = fmaf(kr8[i], vr8[j], acc[i][j]);
        }

        if (tid < DOUT) {
            #pragma unroll
            for (int kk = 0; kk < 16; kk++)
                ksum_local += Ks[kk][tid];
        }
    }

    float* kvout = g_KVpart + (size_t)blockIdx.x * (DOUT * DOUT);
    #pragma unroll
    for (int i = 0; i < 8; i++) {
        float* row = kvout + (size_t)(mr + i) * DOUT + mc;
        *(float4*)(row)     = make_float4(acc[i][0], acc[i][1], acc[i][2], acc[i][3]);
        *(float4*)(row + 4) = make_float4(acc[i][4], acc[i][5], acc[i][6], acc[i][7]);
    }
    if (tid < DOUT)
        g_kspart[(size_t)blockIdx.x * DOUT + tid] = ksum_local;
}

// ============================================================================
// Reduce partials -> g_KV, g_ksum.
// ============================================================================
__global__ void reduce_kernel()
{
    const int i = blockIdx.x * blockDim.x + threadIdx.x;
    if (i < DOUT * DOUT) {
        float s = 0.0f;
        for (int b = 0; b < NB; b++)
            s += g_KVpart[(size_t)b * (DOUT * DOUT) + i];
        g_KV[i] = s;
    } else {
        const int j = i - DOUT * DOUT;
        if (j < DOUT) {
            float s = 0.0f;
            for (int b = 0; b < NB; b++)
                s += g_kspart[(size_t)b * DOUT + j];
            g_ksum[j] = s;
        }
    }
}

// ============================================================================
// Kernel C: out = elu((Q @ KV) * (1 / (Q @ ksum)))  — Q loaded fp16.
// ============================================================================
#define SMEMC_FLOATS (DOUT * DOUT + DOUT * 68 + DOUT + 64)

__global__ __launch_bounds__(256) void out_kernel(float* __restrict__ out)
{
    extern __shared__ float smf[];
    float* KVs    = smf;
    float* Qs     = smf + DOUT * DOUT;
    float* ksum_s = Qs + DOUT * 68;
    float* z_s    = ksum_s + DOUT;

    const int tid  = threadIdx.x;
    const int row0 = blockIdx.x * 64;

    for (int i = tid; i < (DOUT * DOUT) / 4; i += 256)
        ((float4*)KVs)[i] = ((const float4*)g_KV)[i];
    if (tid < DOUT)
        ksum_s[tid] = g_ksum[tid];

    // stage Q tile transposed (fp16 -> fp32): 64 rows x 16 uint4 (8 halves each)
    for (int i = tid; i < 1024; i += 256) {
        const int r   = i >> 4;
        const int cq8 = (i & 15) * 8;
        uint4 raw = *(const uint4*)(g_Q + (size_t)(row0 + r) * DOUT + cq8);
        const uint32_t* w = &raw.x;
        #pragma unroll
        for (int q = 0; q < 4; q++) {
            float2 f = __half22float2(*(const __half2*)&w[q]);
            Qs[(cq8 + 2*q)     * 68 + r] = f.x;
            Qs[(cq8 + 2*q + 1) * 68 + r] = f.y;
        }
    }
    __syncthreads();

    if (tid < 64) {
        float dot = 0.0f;
        #pragma unroll 8
        for (int k = 0; k < DOUT; k++)
            dot = fmaf(Qs[k * 68 + tid], ksum_s[k], dot);
        z_s[tid] = 1.0f / dot;
    }
    __syncthreads();

    const int cg = tid & 15;
    const int rg = tid >> 4;
    const int mc = cg * 8;
    const int mr = rg * 4;

    float acc[4][8];
    #pragma unroll
    for (int i = 0; i < 4; i++)
        #pragma unroll
        for (int j = 0; j < 8; j++) acc[i][j] = 0.0f;

    #pragma unroll 8
    for (int kk = 0; kk < DOUT; kk++) {
        float4 a  = *(const float4*)&Qs[kk * 68 + mr];
        float4 b0 = *(const float4*)&KVs[kk * DOUT + mc];
        float4 b1 = *(const float4*)&KVs[kk * DOUT + mc + 4];
        float ar[4] = {a.x, a.y, a.z, a.w};
        float br[8] = {b0.x, b0.y, b0.z, b0.w, b1.x, b1.y, b1.z, b1.w};
        #pragma unroll
        for (int i = 0; i < 4; i++)
            #pragma unroll
            for (int j = 0; j < 8; j++)
                acc[i][j] = fmaf(ar[i], br[j], acc[i][j]);
    }

    #pragma unroll
    for (int i = 0; i < 4; i++) {
        const float z = z_s[mr + i];
        float v[8];
        #pragma unroll
        for (int j = 0; j < 8; j++) {
            float x = acc[i][j] * z;
            v[j] = x > 0.0f ? x : expm1f(x);
        }
        float* orow = out + (size_t)(row0 + mr + i) * DOUT + mc;
        *(float4*)(orow)     = make_float4(v[0], v[1], v[2], v[3]);
        *(float4*)(orow + 4) = make_float4(v[4], v[5], v[6], v[7]);
    }
}

// ============================================================================
// Launch
// ============================================================================
extern "C" void kernel_launch(void* const* d_in, const int* in_sizes, int n_in,
                              void* d_out, int out_size)
{
    const float* h  = (const float*)d_in[0];
    const float* Wq = (const float*)d_in[1];
    const float* Wk = (const float*)d_in[2];
    const float* Wv = (const float*)d_in[3];
    float* out = (float*)d_out;

    cudaFuncSetAttribute(qkv_mma, cudaFuncAttributeMaxDynamicSharedMemorySize, SM_QKV_TOTAL);
    const int smemC = SMEMC_FLOATS * (int)sizeof(float);
    cudaFuncSetAttribute(out_kernel, cudaFuncAttributeMaxDynamicSharedMemorySize, smemC);

    convert_w<<<(DIN * NQKV + 255) / 256, 256>>>(Wq, Wk, Wv);

    dim3 gridA(3, NBLK_M);
    qkv_mma<<<gridA, 256, SM_QKV_TOTAL>>>(h);

    kv_kernel<<<NB, 256>>>();
    reduce_kernel<<<(DOUT * DOUT + DOUT + 255) / 256, 256>>>();
    out_kernel<<<NROWS / 64, 256, smemC>>>(out);
}

// round 6
// speedup vs baseline: 3.7865x; 1.5848x over previous
#include <cuda_runtime.h>
#include <cuda_fp16.h>
#include <math.h>
#include <stdint.h>

#define NROWS 200000
#define DIN   512
#define DOUT  128
#define NQKV  384
#define BK    32
#define NCHUNKS (DIN / BK)                    // 16
#define MTILE 128
#define NBLK_M ((NROWS + MTILE - 1) / MTILE)  // 1563

#define CHUNK 512
#define NB    ((NROWS + CHUNK - 1) / CHUNK)   // 391

#define KV_SCALE_LOG2 6
#define KV_SCALE_INV  (1.0f / 64.0f)
#define KV_SCALE      64.0f

// ---- scratch (device globals; no runtime allocation) ----
__device__ __half g_Q[(size_t)NROWS * DOUT];
__device__ __half g_K[(size_t)NROWS * DOUT];
__device__ __half g_V[(size_t)NROWS * DOUT];
__device__ float g_KVpart[(size_t)NB * DOUT * DOUT];
__device__ float g_kspart[(size_t)NB * DOUT];
__device__ __half g_KVhi[DOUT * DOUT];   // KV * 2^-6, hi part
__device__ __half g_KVlo[DOUT * DOUT];   // KV * 2^-6, lo part
__device__ float g_ksum[DOUT];

// fp16 weights, row-major [k][384]
__device__ __half g_Wh[(size_t)DIN * NQKV];

// ---- qkv smem layout ----
#define A_ROW_B   80
#define A_STAGE_B (MTILE * A_ROW_B)        // 10240
#define B_ROW_B   272
#define B_STAGE_B (BK * B_ROW_B)           // 8704
#define SM_B_OFF  (2 * A_STAGE_B)          // 20480
#define SM_QKV_TOTAL (SM_B_OFF + 2 * B_STAGE_B)  // 37888

// ---- kv smem layout ----
#define KVT_ROW_B  272
#define KVT_TILE_B (32 * KVT_ROW_B)        // 8704

// ---- out smem layout (dynamic) ----
#define OUT_Q_OFF   0
#define OUT_Q_B     (64 * 272)             // 17408
#define OUT_HI_OFF  (OUT_Q_OFF + OUT_Q_B)
#define OUT_KV_B    (128 * 272)            // 34816
#define OUT_LO_OFF  (OUT_HI_OFF + OUT_KV_B)
#define OUT_KS_OFF  (OUT_LO_OFF + OUT_KV_B)          // fp32[128]
#define OUT_Z_OFF   (OUT_KS_OFF + 128 * 4)           // fp32[64]
#define OUT_SM_TOTAL (OUT_Z_OFF + 64 * 4)            // 88064

static __device__ __forceinline__ uint32_t smem_u32(const void* p) {
    uint32_t a;
    asm("{ .reg .u64 t; cvta.to.shared.u64 t, %1; cvt.u32.u64 %0, t; }" : "=r"(a) : "l"(p));
    return a;
}
static __device__ __forceinline__ void cp16(uint32_t dst, const void* src) {
    asm volatile("cp.async.cg.shared.global [%0], [%1], 16;" :: "r"(dst), "l"(src) : "memory");
}
static __device__ __forceinline__ void cp16z(uint32_t dst, const void* src, int sz) {
    asm volatile("cp.async.cg.shared.global [%0], [%1], 16, %2;"
                 :: "r"(dst), "l"(src), "r"(sz) : "memory");
}
#define CP_COMMIT()  asm volatile("cp.async.commit_group;" ::: "memory")
#define CP_WAIT(N)   asm volatile("cp.async.wait_group %0;" :: "n"(N) : "memory")

static __device__ __forceinline__ void ldsm_x4(uint32_t* r, uint32_t addr) {
    asm volatile("ldmatrix.sync.aligned.m8n8.x4.shared.b16 {%0,%1,%2,%3}, [%4];"
                 : "=r"(r[0]), "=r"(r[1]), "=r"(r[2]), "=r"(r[3]) : "r"(addr));
}
static __device__ __forceinline__ void ldsm_x4_t(uint32_t* r, uint32_t addr) {
    asm volatile("ldmatrix.sync.aligned.m8n8.x4.trans.shared.b16 {%0,%1,%2,%3}, [%4];"
                 : "=r"(r[0]), "=r"(r[1]), "=r"(r[2]), "=r"(r[3]) : "r"(addr));
}
static __device__ __forceinline__ void mma16816h(float* d, const uint32_t* a,
                                                 const uint32_t* b) {
    asm volatile(
        "mma.sync.aligned.m16n8k16.row.col.f32.f16.f16.f32 "
        "{%0,%1,%2,%3}, {%4,%5,%6,%7}, {%8,%9}, {%0,%1,%2,%3};"
        : "+f"(d[0]), "+f"(d[1]), "+f"(d[2]), "+f"(d[3])
        : "r"(a[0]), "r"(a[1]), "r"(a[2]), "r"(a[3]), "r"(b[0]), "r"(b[1]));
}

__device__ __forceinline__ float elu_p1(float x) {
    return x > 0.0f ? x + 1.0f : expf(x);
}

// ============================================================================
// Kernel W: fp16 weight conversion into [k][384].
// ============================================================================
__global__ void convert_w(const float* __restrict__ Wq,
                          const float* __restrict__ Wk,
                          const float* __restrict__ Wv)
{
    int idx = blockIdx.x * 256 + threadIdx.x;
    if (idx >= DIN * NQKV) return;
    int k = idx / NQKV;
    int n = idx % NQKV;
    const float* W = (n < 128) ? Wq : (n < 256) ? Wk : Wv;
    g_Wh[idx] = __float2half_rn(W[(size_t)k * DOUT + (n & 127)]);
}

// ============================================================================
// Kernel A: [Q|K|V] = f(h @ W_which) via single-pass fp16 mma.sync.
// ============================================================================
__global__ __launch_bounds__(256, 1) void qkv_mma(const float* __restrict__ h)
{
    extern __shared__ __align__(256) unsigned char sm[];
    const uint32_t sbase = smem_u32(sm);

    const int which = blockIdx.x;
    const int row0  = blockIdx.y * MTILE;
    const int tid   = threadIdx.x;
    const int wid   = tid >> 5;
    const int lane  = tid & 31;

    const int wm = wid & 3;
    const int wn = wid >> 2;
    const int m0 = wm * 32;
    const int n0w = wn * 64;

    const int arow = tid >> 1;
    const int aseg = (tid & 1) * 16;
    int lrow = row0 + arow;
    if (lrow >= NROWS) lrow = NROWS - 1;
    const float* hrow = h + (size_t)lrow * DIN + aseg;
    const uint32_t a_sts_off = (uint32_t)(arow * A_ROW_B + aseg * 2);

    const int nbase = which * 128;

    float acc[2][8][4];
    #pragma unroll
    for (int i = 0; i < 2; i++)
        #pragma unroll
        for (int j = 0; j < 8; j++)
            #pragma unroll
            for (int r = 0; r < 4; r++) acc[i][j][r] = 0.0f;

    const int a_r = (lane & 7) + (lane & 8);
    const int a_c = ((lane >> 4) & 1) * 8;
    const int b_k = (lane & 7) + (lane & 8);
    const int b_n = ((lane >> 4) & 1) * 8;

    auto issue_B = [&](int c, int stage) {
        const size_t src_row0 = (size_t)(c * BK) * NQKV + nbase;
        uint32_t dstb = sbase + SM_B_OFF + stage * B_STAGE_B;
        #pragma unroll
        for (int it = 0; it < 2; it++) {
            int idx = tid + it * 256;
            int r = idx >> 4, c16 = idx & 15;
            cp16(dstb + r * B_ROW_B + c16 * 16,
                 g_Wh + src_row0 + (size_t)r * NQKV + c16 * 8);
        }
        CP_COMMIT();
    };
    auto sts_A = [&](int stage, const float4* v) {
        uint32_t hx[8];
        #pragma unroll
        for (int j = 0; j < 4; j++) {
            __half2 p0 = __floats2half2_rn(v[j].x, v[j].y);
            __half2 p1 = __floats2half2_rn(v[j].z, v[j].w);
            hx[2*j]   = *(uint32_t*)&p0;
            hx[2*j+1] = *(uint32_t*)&p1;
        }
        uint32_t dst = sbase + stage * A_STAGE_B + a_sts_off;
        asm volatile("st.shared.v4.b32 [%0], {%1,%2,%3,%4};" :: "r"(dst),
                     "r"(hx[0]),"r"(hx[1]),"r"(hx[2]),"r"(hx[3]));
        asm volatile("st.shared.v4.b32 [%0], {%1,%2,%3,%4};" :: "r"(dst+16),
                     "r"(hx[4]),"r"(hx[5]),"r"(hx[6]),"r"(hx[7]));
    };

    // prologue: B0 + A0
    float4 v[4];
    #pragma unroll
    for (int j = 0; j < 4; j++) v[j] = *(const float4*)(hrow + 4 * j);
    issue_B(0, 0);
    sts_A(0, v);

    for (int c = 0; c < NCHUNKS; c++) {
        const int stage = c & 1;

        if (c + 1 < NCHUNKS) {
            #pragma unroll
            for (int j = 0; j < 4; j++)
                v[j] = *(const float4*)(hrow + (c + 1) * BK + 4 * j);
        }
        CP_WAIT(0);
        __syncthreads();               // B(c) landed; all readers of stage^1 done
        if (c + 1 < NCHUNKS) issue_B(c + 1, stage ^ 1);

        const uint32_t Ab = sbase + stage * A_STAGE_B;
        const uint32_t Bb = sbase + SM_B_OFF + stage * B_STAGE_B;
        #pragma unroll
        for (int ks = 0; ks < 2; ks++) {
            const int k0 = ks * 16;
            uint32_t afr[2][4];
            #pragma unroll
            for (int im = 0; im < 2; im++)
                ldsm_x4(afr[im], Ab + (uint32_t)((m0 + im * 16 + a_r) * A_ROW_B +
                                                 (k0 + a_c) * 2));
            uint32_t bfr[4][4];
            #pragma unroll
            for (int jn = 0; jn < 4; jn++)
                ldsm_x4_t(bfr[jn], Bb + (uint32_t)((k0 + b_k) * B_ROW_B +
                                                   (n0w + jn * 16 + b_n) * 2));
            #pragma unroll
            for (int im = 0; im < 2; im++)
                #pragma unroll
                for (int jn = 0; jn < 4; jn++) {
                    mma16816h(acc[im][jn * 2 + 0], afr[im], &bfr[jn][0]);
                    mma16816h(acc[im][jn * 2 + 1], afr[im], &bfr[jn][2]);
                }
        }

        if (c + 1 < NCHUNKS) sts_A(stage ^ 1, v);
    }

    __half* Out = (which == 0) ? g_Q : (which == 1) ? g_K : g_V;
    const bool act = (which < 2);
    const int g = lane >> 2;
    const int t = lane & 3;

    #pragma unroll
    for (int im = 0; im < 2; im++) {
        const int r0 = row0 + m0 + im * 16 + g;
        const int r1 = r0 + 8;
        #pragma unroll
        for (int j = 0; j < 8; j++) {
            const int col = n0w + j * 8 + t * 2;
            float c0 = acc[im][j][0], c1 = acc[im][j][1];
            float c2 = acc[im][j][2], c3 = acc[im][j][3];
            if (act) {
                c0 = elu_p1(c0); c1 = elu_p1(c1);
                c2 = elu_p1(c2); c3 = elu_p1(c3);
            }
            if (r0 < NROWS)
                *(__half2*)(Out + (size_t)r0 * DOUT + col) = __floats2half2_rn(c0, c1);
            if (r1 < NROWS)
                *(__half2*)(Out + (size_t)r1 * DOUT + col) = __floats2half2_rn(c2, c3);
        }
    }
}

// ============================================================================
// Kernel B: partial KV = K_chunk^T @ V_chunk via fp16 mma, plus partial k_sum.
// A = K^T from trans ldmatrix (tile-reordered), B = V from trans ldmatrix.
// ============================================================================
__global__ __launch_bounds__(256) void kv_mma()
{
    __shared__ __align__(16) unsigned char sm[2 * 2 * KVT_TILE_B];  // 34816
    const uint32_t sb = smem_u32(sm);

    const int tid  = threadIdx.x;
    const int wid  = tid >> 5;
    const int lane = tid & 31;
    const int m0 = (wid & 3) * 32;     // K-feature rows
    const int n0 = (wid >> 2) * 64;    // V-feature cols
    const int base = blockIdx.x * CHUNK;

    float acc[2][8][4];
    #pragma unroll
    for (int i = 0; i < 2; i++)
        #pragma unroll
        for (int j = 0; j < 8; j++)
            #pragma unroll
            for (int r = 0; r < 4; r++) acc[i][j][r] = 0.0f;
    float ks0 = 0.0f, ks1 = 0.0f;

    auto issue = [&](int it, int stage) {
        #pragma unroll
        for (int q = 0; q < 4; q++) {
            int idx  = tid + q * 256;          // 1024 chunks
            int tile = idx >> 9;               // 0=K, 1=V
            int row  = (idx >> 4) & 31;
            int c16  = idx & 15;
            int grow = base + it * 32 + row;
            const __half* src = (tile ? g_V : g_K) + (size_t)grow * DOUT + c16 * 8;
            uint32_t dst = sb + stage * 2 * KVT_TILE_B + tile * KVT_TILE_B +
                           row * KVT_ROW_B + c16 * 16;
            cp16z(dst, src, (grow < NROWS) ? 16 : 0);
        }
        CP_COMMIT();
    };

    const int trow = (lane & 7) + (lane & 8);
    const int tcol = ((lane >> 4) & 1) * 8;

    issue(0, 0);

    for (int it = 0; it < 16; it++) {
        const int stage = it & 1;
        CP_WAIT(0);
        __syncthreads();
        if (it + 1 < 16) issue(it + 1, stage ^ 1);

        const uint32_t Kb = sb + stage * 2 * KVT_TILE_B;
        const uint32_t Vb = Kb + KVT_TILE_B;

        #pragma unroll
        for (int ks = 0; ks < 2; ks++) {
            const int k0 = ks * 16;
            uint32_t afr[2][4];
            #pragma unroll
            for (int im = 0; im < 2; im++) {
                uint32_t t4[4];
                ldsm_x4_t(t4, Kb + (uint32_t)((k0 + trow) * KVT_ROW_B +
                                              (m0 + im * 16 + tcol) * 2));
                afr[im][0] = t4[0]; afr[im][1] = t4[2];   // tile reorder for A
                afr[im][2] = t4[1]; afr[im][3] = t4[3];
            }
            uint32_t bfr[4][4];
            #pragma unroll
            for (int jn = 0; jn < 4; jn++)
                ldsm_x4_t(bfr[jn], Vb + (uint32_t)((k0 + trow) * KVT_ROW_B +
                                                   (n0 + jn * 16 + tcol) * 2));
            #pragma unroll
            for (int im = 0; im < 2; im++)
                #pragma unroll
                for (int jn = 0; jn < 4; jn++) {
                    mma16816h(acc[im][jn * 2 + 0], afr[im], &bfr[jn][0]);
                    mma16816h(acc[im][jn * 2 + 1], afr[im], &bfr[jn][2]);
                }
        }

        if (tid < DOUT) {
            const __half* kp = (const __half*)(sm + stage * 2 * KVT_TILE_B);
            #pragma unroll
            for (int r = 0; r < 32; r += 2) {
                ks0 += __half2float(kp[r * 136 + tid]);
                ks1 += __half2float(kp[(r + 1) * 136 + tid]);
            }
        }
    }

    float* kvout = g_KVpart + (size_t)blockIdx.x * (DOUT * DOUT);
    const int g = lane >> 2;
    const int t = lane & 3;
    #pragma unroll
    for (int im = 0; im < 2; im++) {
        const int r0 = m0 + im * 16 + g;
        #pragma unroll
        for (int j = 0; j < 8; j++) {
            const int col = n0 + j * 8 + t * 2;
            *(float2*)(kvout + (size_t)r0 * DOUT + col) =
                make_float2(acc[im][j][0], acc[im][j][1]);
            *(float2*)(kvout + (size_t)(r0 + 8) * DOUT + col) =
                make_float2(acc[im][j][2], acc[im][j][3]);
        }
    }
    if (tid < DOUT)
        g_kspart[(size_t)blockIdx.x * DOUT + tid] = ks0 + ks1;
}

// ============================================================================
// Reduce partials -> KV (scaled fp16 hi/lo), ksum (fp32).
// ============================================================================
__global__ void reduce_kernel()
{
    const int i = blockIdx.x * blockDim.x + threadIdx.x;
    if (i < DOUT * DOUT) {
        float s = 0.0f;
        for (int b = 0; b < NB; b++)
            s += g_KVpart[(size_t)b * (DOUT * DOUT) + i];
        s *= KV_SCALE_INV;
        __half hi = __float2half_rn(s);
        __half lo = __float2half_rn(s - __half2float(hi));
        g_KVhi[i] = hi;
        g_KVlo[i] = lo;
    } else {
        const int j = i - DOUT * DOUT;
        if (j < DOUT) {
            float s = 0.0f;
            for (int b = 0; b < NB; b++)
                s += g_kspart[(size_t)b * DOUT + j];
            g_ksum[j] = s;
        }
    }
}

// ============================================================================
// Kernel C: out = elu((Q @ KV) * (1 / (Q @ ksum))) via fp16 mma.
// 64-row tiles; Q + KVhi + KVlo staged once per block.
// ============================================================================
__global__ __launch_bounds__(256) void out_mma(float* __restrict__ out)
{
    extern __shared__ __align__(256) unsigned char smo[];
    const uint32_t sb = smem_u32(smo);

    const int tid  = threadIdx.x;
    const int wid  = tid >> 5;
    const int lane = tid & 31;
    const int row0 = blockIdx.x * 64;

    const int m0 = (wid & 1) * 32;
    const int n0 = (wid >> 1) * 32;

    // stage Q: 1024 chunks (64 rows x 16)
    #pragma unroll
    for (int q = 0; q < 4; q++) {
        int idx = tid + q * 256;
        int r = idx >> 4, c16 = idx & 15;
        cp16(sb + OUT_Q_OFF + r * 272 + c16 * 16,
             g_Q + (size_t)(row0 + r) * DOUT + c16 * 8);
    }
    // stage KVhi/KVlo: 4096 chunks
    #pragma unroll
    for (int q = 0; q < 16; q++) {
        int idx = tid + q * 256;
        int part = idx >> 11;
        int rem = idx & 2047;
        int r = rem >> 4, c16 = rem & 15;
        const __half* src = (part ? g_KVlo : g_KVhi) + r * DOUT + c16 * 8;
        cp16(sb + (part ? OUT_LO_OFF : OUT_HI_OFF) + r * 272 + c16 * 16, src);
    }
    CP_COMMIT();
    float* ksum_s = (float*)(smo + OUT_KS_OFF);
    float* z_s    = (float*)(smo + OUT_Z_OFF);
    if (tid < DOUT) ksum_s[tid] = g_ksum[tid];
    CP_WAIT(0);
    __syncthreads();

    // z = 1 / (Q . ksum) per row
    if (tid < 64) {
        const __half* qp = (const __half*)(smo + OUT_Q_OFF) + tid * 136;
        float d0 = 0.0f, d1 = 0.0f;
        #pragma unroll
        for (int k = 0; k < DOUT; k += 2) {
            d0 = fmaf(__half2float(qp[k]),     ksum_s[k],     d0);
            d1 = fmaf(__half2float(qp[k + 1]), ksum_s[k + 1], d1);
        }
        z_s[tid] = 1.0f / (d0 + d1);
    }

    float acc[2][4][4];
    #pragma unroll
    for (int i = 0; i < 2; i++)
        #pragma unroll
        for (int j = 0; j < 4; j++)
            #pragma unroll
            for (int r = 0; r < 4; r++) acc[i][j][r] = 0.0f;

    const int a_r = (lane & 7) + (lane & 8);
    const int a_c = ((lane >> 4) & 1) * 8;

    #pragma unroll
    for (int ks = 0; ks < 8; ks++) {
        const int k0 = ks * 16;
        uint32_t afr[2][4];
        #pragma unroll
        for (int im = 0; im < 2; im++)
            ldsm_x4(afr[im], sb + OUT_Q_OFF +
                    (uint32_t)((m0 + im * 16 + a_r) * 272 + (k0 + a_c) * 2));
        #pragma unroll
        for (int part = 0; part < 2; part++) {
            const uint32_t Bb = sb + (part ? OUT_LO_OFF : OUT_HI_OFF);
            uint32_t bfr[2][4];
            #pragma unroll
            for (int jn = 0; jn < 2; jn++)
                ldsm_x4_t(bfr[jn], Bb + (uint32_t)((k0 + a_r) * 272 +
                                                   (n0 + jn * 16 + a_c) * 2));
            #pragma unroll
            for (int im = 0; im < 2; im++)
                #pragma unroll
                for (int jn = 0; jn < 2; jn++) {
                    mma16816h(acc[im][jn * 2 + 0], afr[im], &bfr[jn][0]);
                    mma16816h(acc[im][jn * 2 + 1], afr[im], &bfr[jn][2]);
                }
        }
    }
    __syncthreads();   // z_s ready (warp 0/1 computed it before mma; barrier for safety)

    const int g = lane >> 2;
    const int t = lane & 3;
    #pragma unroll
    for (int im = 0; im < 2; im++) {
        const int lr0 = m0 + im * 16 + g;
        const int lr1 = lr0 + 8;
        const float z0 = z_s[lr0] * KV_SCALE;
        const float z1 = z_s[lr1] * KV_SCALE;
        #pragma unroll
        for (int j = 0; j < 4; j++) {
            const int col = n0 + j * 8 + t * 2;
            float x0 = acc[im][j][0] * z0;
            float x1 = acc[im][j][1] * z0;
            float x2 = acc[im][j][2] * z1;
            float x3 = acc[im][j][3] * z1;
            x0 = x0 > 0.0f ? x0 : expm1f(x0);
            x1 = x1 > 0.0f ? x1 : expm1f(x1);
            x2 = x2 > 0.0f ? x2 : expm1f(x2);
            x3 = x3 > 0.0f ? x3 : expm1f(x3);
            *(float2*)(out + (size_t)(row0 + lr0) * DOUT + col) = make_float2(x0, x1);
            *(float2*)(out + (size_t)(row0 + lr1) * DOUT + col) = make_float2(x2, x3);
        }
    }
}

// ============================================================================
// Launch
// ============================================================================
extern "C" void kernel_launch(void* const* d_in, const int* in_sizes, int n_in,
                              void* d_out, int out_size)
{
    const float* h  = (const float*)d_in[0];
    const float* Wq = (const float*)d_in[1];
    const float* Wk = (const float*)d_in[2];
    const float* Wv = (const float*)d_in[3];
    float* out = (float*)d_out;

    cudaFuncSetAttribute(qkv_mma, cudaFuncAttributeMaxDynamicSharedMemorySize, SM_QKV_TOTAL);
    cudaFuncSetAttribute(out_mma, cudaFuncAttributeMaxDynamicSharedMemorySize, OUT_SM_TOTAL);

    convert_w<<<(DIN * NQKV + 255) / 256, 256>>>(Wq, Wk, Wv);

    dim3 gridA(3, NBLK_M);
    qkv_mma<<<gridA, 256, SM_QKV_TOTAL>>>(h);

    kv_mma<<<NB, 256>>>();
    reduce_kernel<<<(DOUT * DOUT + DOUT + 255) / 256, 256>>>();
    out_mma<<<NROWS / 64, 256, OUT_SM_TOTAL>>>(out);
}

// round 7
// speedup vs baseline: 4.7840x; 1.2634x over previous
#include <cuda_runtime.h>
#include <cuda_fp16.h>
#include <math.h>
#include <stdint.h>

#define NROWS 200000
#define DIN   512
#define DOUT  128
#define NQKV  384
#define BK    32
#define NCHUNKS (DIN / BK)                    // 16
#define MTILE 128
#define NBLK_M ((NROWS + MTILE - 1) / MTILE)  // 1563

#define CHUNK 512
#define NB    ((NROWS + CHUNK - 1) / CHUNK)   // 391

#define KV_SCALE_INV  (1.0f / 64.0f)
// ksum stored fp16 scaled by 1/8; KV scaled by 1/64 -> z_eff = 64 * 0.125 / den = 8/den

// ---- scratch (device globals; no runtime allocation) ----
__device__ __half g_Q[(size_t)NROWS * DOUT];
__device__ __half g_K[(size_t)NROWS * DOUT];
__device__ __half g_V[(size_t)NROWS * DOUT];
__device__ float g_KVpart[(size_t)NB * DOUT * DOUT];
__device__ float g_kspart[(size_t)NB * DOUT];
__device__ __half g_KVhi[DOUT * DOUT];   // KV * 2^-6, hi
__device__ __half g_KVlo[DOUT * DOUT];   // KV * 2^-6, lo
__device__ __half g_kshi16[DOUT];        // ksum * 2^-3, hi
__device__ __half g_kslo16[DOUT];        // ksum * 2^-3, lo

// fp16 weights, row-major [k][384]
__device__ __half g_Wh[(size_t)DIN * NQKV];

// ---- qkv smem layout ----
#define A_ROW_B   80
#define A_STAGE_B (MTILE * A_ROW_B)        // 10240
#define B_ROW_B   272
#define B_STAGE_B (BK * B_ROW_B)           // 8704
#define SM_B_OFF  (2 * A_STAGE_B)          // 20480
#define SM_QKV_TOTAL (SM_B_OFF + 2 * B_STAGE_B)  // 37888

// ---- kv smem layout ----
#define KVT_ROW_B  272
#define KVT_TILE_B (32 * KVT_ROW_B)        // 8704

// ---- out smem layout (dynamic) ----
#define OUT_Q_OFF   0
#define OUT_Q_B     (64 * 272)             // 17408
#define OUT_HI_OFF  (OUT_Q_OFF + OUT_Q_B)
#define OUT_KV_B    (128 * 272)            // 34816
#define OUT_LO_OFF  (OUT_HI_OFF + OUT_KV_B)
#define OUT_KS_OFF  (OUT_LO_OFF + OUT_KV_B)          // 256 halves: [hi|lo]
#define OUT_SM_TOTAL (OUT_KS_OFF + 256 * 2)          // 87552

static __device__ __forceinline__ uint32_t smem_u32(const void* p) {
    uint32_t a;
    asm("{ .reg .u64 t; cvta.to.shared.u64 t, %1; cvt.u32.u64 %0, t; }" : "=r"(a) : "l"(p));
    return a;
}
static __device__ __forceinline__ void cp16(uint32_t dst, const void* src) {
    asm volatile("cp.async.cg.shared.global [%0], [%1], 16;" :: "r"(dst), "l"(src) : "memory");
}
static __device__ __forceinline__ void cp16z(uint32_t dst, const void* src, int sz) {
    asm volatile("cp.async.cg.shared.global [%0], [%1], 16, %2;"
                 :: "r"(dst), "l"(src), "r"(sz) : "memory");
}
#define CP_COMMIT()  asm volatile("cp.async.commit_group;" ::: "memory")
#define CP_WAIT(N)   asm volatile("cp.async.wait_group %0;" :: "n"(N) : "memory")

static __device__ __forceinline__ void ldsm_x4(uint32_t* r, uint32_t addr) {
    asm volatile("ldmatrix.sync.aligned.m8n8.x4.shared.b16 {%0,%1,%2,%3}, [%4];"
                 : "=r"(r[0]), "=r"(r[1]), "=r"(r[2]), "=r"(r[3]) : "r"(addr));
}
static __device__ __forceinline__ void ldsm_x4_t(uint32_t* r, uint32_t addr) {
    asm volatile("ldmatrix.sync.aligned.m8n8.x4.trans.shared.b16 {%0,%1,%2,%3}, [%4];"
                 : "=r"(r[0]), "=r"(r[1]), "=r"(r[2]), "=r"(r[3]) : "r"(addr));
}
static __device__ __forceinline__ void mma16816h(float* d, const uint32_t* a,
                                                 const uint32_t* b) {
    asm volatile(
        "mma.sync.aligned.m16n8k16.row.col.f32.f16.f16.f32 "
        "{%0,%1,%2,%3}, {%4,%5,%6,%7}, {%8,%9}, {%0,%1,%2,%3};"
        : "+f"(d[0]), "+f"(d[1]), "+f"(d[2]), "+f"(d[3])
        : "r"(a[0]), "r"(a[1]), "r"(a[2]), "r"(a[3]), "r"(b[0]), "r"(b[1]));
}

__device__ __forceinline__ float elu_p1(float x) {
    return x > 0.0f ? x + 1.0f : expf(x);
}

// ============================================================================
// Kernel W: fp16 weight conversion into [k][384].
// ============================================================================
__global__ void convert_w(const float* __restrict__ Wq,
                          const float* __restrict__ Wk,
                          const float* __restrict__ Wv)
{
    int idx = blockIdx.x * 256 + threadIdx.x;
    if (idx >= DIN * NQKV) return;
    int k = idx / NQKV;
    int n = idx % NQKV;
    const float* W = (n < 128) ? Wq : (n < 256) ? Wk : Wv;
    g_Wh[idx] = __float2half_rn(W[(size_t)k * DOUT + (n & 127)]);
}

// ============================================================================
// Kernel A: [Q|K|V] = f(h @ W_which) via single-pass fp16 mma.sync.
// launch_bounds(256,2): cap regs at 128 so 2 CTAs co-reside per SM.
// ============================================================================
__global__ __launch_bounds__(256, 2) void qkv_mma(const float* __restrict__ h)
{
    extern __shared__ __align__(256) unsigned char sm[];
    const uint32_t sbase = smem_u32(sm);

    const int which = blockIdx.x;
    const int row0  = blockIdx.y * MTILE;
    const int tid   = threadIdx.x;
    const int wid   = tid >> 5;
    const int lane  = tid & 31;

    const int wm = wid & 3;
    const int wn = wid >> 2;
    const int m0 = wm * 32;
    const int n0w = wn * 64;

    const int arow = tid >> 1;
    const int aseg = (tid & 1) * 16;
    int lrow = row0 + arow;
    if (lrow >= NROWS) lrow = NROWS - 1;
    const float* hrow = h + (size_t)lrow * DIN + aseg;
    const uint32_t a_sts_off = (uint32_t)(arow * A_ROW_B + aseg * 2);

    const int nbase = which * 128;

    float acc[2][8][4];
    #pragma unroll
    for (int i = 0; i < 2; i++)
        #pragma unroll
        for (int j = 0; j < 8; j++)
            #pragma unroll
            for (int r = 0; r < 4; r++) acc[i][j][r] = 0.0f;

    const int a_r = (lane & 7) + (lane & 8);
    const int a_c = ((lane >> 4) & 1) * 8;
    const int b_k = (lane & 7) + (lane & 8);
    const int b_n = ((lane >> 4) & 1) * 8;

    auto issue_B = [&](int c, int stage) {
        const size_t src_row0 = (size_t)(c * BK) * NQKV + nbase;
        uint32_t dstb = sbase + SM_B_OFF + stage * B_STAGE_B;
        #pragma unroll
        for (int it = 0; it < 2; it++) {
            int idx = tid + it * 256;
            int r = idx >> 4, c16 = idx & 15;
            cp16(dstb + r * B_ROW_B + c16 * 16,
                 g_Wh + src_row0 + (size_t)r * NQKV + c16 * 8);
        }
        CP_COMMIT();
    };
    auto sts_A = [&](int stage, const float4* v) {
        uint32_t hx[8];
        #pragma unroll
        for (int j = 0; j < 4; j++) {
            __half2 p0 = __floats2half2_rn(v[j].x, v[j].y);
            __half2 p1 = __floats2half2_rn(v[j].z, v[j].w);
            hx[2*j]   = *(uint32_t*)&p0;
            hx[2*j+1] = *(uint32_t*)&p1;
        }
        uint32_t dst = sbase + stage * A_STAGE_B + a_sts_off;
        asm volatile("st.shared.v4.b32 [%0], {%1,%2,%3,%4};" :: "r"(dst),
                     "r"(hx[0]),"r"(hx[1]),"r"(hx[2]),"r"(hx[3]));
        asm volatile("st.shared.v4.b32 [%0], {%1,%2,%3,%4};" :: "r"(dst+16),
                     "r"(hx[4]),"r"(hx[5]),"r"(hx[6]),"r"(hx[7]));
    };

    float4 v[4];
    #pragma unroll
    for (int j = 0; j < 4; j++) v[j] = *(const float4*)(hrow + 4 * j);
    issue_B(0, 0);
    sts_A(0, v);

    for (int c = 0; c < NCHUNKS; c++) {
        const int stage = c & 1;

        if (c + 1 < NCHUNKS) {
            #pragma unroll
            for (int j = 0; j < 4; j++)
                v[j] = *(const float4*)(hrow + (c + 1) * BK + 4 * j);
        }
        CP_WAIT(0);
        __syncthreads();
        if (c + 1 < NCHUNKS) issue_B(c + 1, stage ^ 1);

        const uint32_t Ab = sbase + stage * A_STAGE_B;
        const uint32_t Bb = sbase + SM_B_OFF + stage * B_STAGE_B;
        #pragma unroll
        for (int ks = 0; ks < 2; ks++) {
            const int k0 = ks * 16;
            uint32_t afr[2][4];
            #pragma unroll
            for (int im = 0; im < 2; im++)
                ldsm_x4(afr[im], Ab + (uint32_t)((m0 + im * 16 + a_r) * A_ROW_B +
                                                 (k0 + a_c) * 2));
            uint32_t bfr[4][4];
            #pragma unroll
            for (int jn = 0; jn < 4; jn++)
                ldsm_x4_t(bfr[jn], Bb + (uint32_t)((k0 + b_k) * B_ROW_B +
                                                   (n0w + jn * 16 + b_n) * 2));
            #pragma unroll
            for (int im = 0; im < 2; im++)
                #pragma unroll
                for (int jn = 0; jn < 4; jn++) {
                    mma16816h(acc[im][jn * 2 + 0], afr[im], &bfr[jn][0]);
                    mma16816h(acc[im][jn * 2 + 1], afr[im], &bfr[jn][2]);
                }
        }

        if (c + 1 < NCHUNKS) sts_A(stage ^ 1, v);
    }

    __half* Out = (which == 0) ? g_Q : (which == 1) ? g_K : g_V;
    const bool act = (which < 2);
    const int g = lane >> 2;
    const int t = lane & 3;

    #pragma unroll
    for (int im = 0; im < 2; im++) {
        const int r0 = row0 + m0 + im * 16 + g;
        const int r1 = r0 + 8;
        #pragma unroll
        for (int j = 0; j < 8; j++) {
            const int col = n0w + j * 8 + t * 2;
            float c0 = acc[im][j][0], c1 = acc[im][j][1];
            float c2 = acc[im][j][2], c3 = acc[im][j][3];
            if (act) {
                c0 = elu_p1(c0); c1 = elu_p1(c1);
                c2 = elu_p1(c2); c3 = elu_p1(c3);
            }
            if (r0 < NROWS)
                *(__half2*)(Out + (size_t)r0 * DOUT + col) = __floats2half2_rn(c0, c1);
            if (r1 < NROWS)
                *(__half2*)(Out + (size_t)r1 * DOUT + col) = __floats2half2_rn(c2, c3);
        }
    }
}

// ============================================================================
// Kernel B: partial KV = K_chunk^T @ V_chunk via fp16 mma + partial k_sum
// via MMA against an all-ones B fragment (col 0 = row sums). No scalar loop.
// ============================================================================
__global__ __launch_bounds__(256, 2) void kv_mma()
{
    __shared__ __align__(16) unsigned char sm[2 * 2 * KVT_TILE_B];  // 34816
    const uint32_t sb = smem_u32(sm);

    const int tid  = threadIdx.x;
    const int wid  = tid >> 5;
    const int lane = tid & 31;
    const int m0 = (wid & 3) * 32;     // K-feature rows
    const int n0 = (wid >> 2) * 64;    // V-feature cols
    const int wn = wid >> 2;
    const int base = blockIdx.x * CHUNK;

    float acc[2][8][4];
    #pragma unroll
    for (int i = 0; i < 2; i++)
        #pragma unroll
        for (int j = 0; j < 8; j++)
            #pragma unroll
            for (int r = 0; r < 4; r++) acc[i][j][r] = 0.0f;
    float acc_ks[2][4];
    #pragma unroll
    for (int i = 0; i < 2; i++)
        #pragma unroll
        for (int r = 0; r < 4; r++) acc_ks[i][r] = 0.0f;

    const uint32_t b_ones[2] = {0x3C003C00u, 0x3C003C00u};

    auto issue = [&](int it, int stage) {
        #pragma unroll
        for (int q = 0; q < 4; q++) {
            int idx  = tid + q * 256;
            int tile = idx >> 9;
            int row  = (idx >> 4) & 31;
            int c16  = idx & 15;
            int grow = base + it * 32 + row;
            const __half* src = (tile ? g_V : g_K) + (size_t)grow * DOUT + c16 * 8;
            uint32_t dst = sb + stage * 2 * KVT_TILE_B + tile * KVT_TILE_B +
                           row * KVT_ROW_B + c16 * 16;
            cp16z(dst, src, (grow < NROWS) ? 16 : 0);
        }
        CP_COMMIT();
    };

    const int trow = (lane & 7) + (lane & 8);
    const int tcol = ((lane >> 4) & 1) * 8;

    issue(0, 0);

    for (int it = 0; it < 16; it++) {
        const int stage = it & 1;
        CP_WAIT(0);
        __syncthreads();
        if (it + 1 < 16) issue(it + 1, stage ^ 1);

        const uint32_t Kb = sb + stage * 2 * KVT_TILE_B;
        const uint32_t Vb = Kb + KVT_TILE_B;

        #pragma unroll
        for (int ks = 0; ks < 2; ks++) {
            const int k0 = ks * 16;
            uint32_t afr[2][4];
            #pragma unroll
            for (int im = 0; im < 2; im++) {
                uint32_t t4[4];
                ldsm_x4_t(t4, Kb + (uint32_t)((k0 + trow) * KVT_ROW_B +
                                              (m0 + im * 16 + tcol) * 2));
                afr[im][0] = t4[0]; afr[im][1] = t4[2];
                afr[im][2] = t4[1]; afr[im][3] = t4[3];
            }
            uint32_t bfr[4][4];
            #pragma unroll
            for (int jn = 0; jn < 4; jn++)
                ldsm_x4_t(bfr[jn], Vb + (uint32_t)((k0 + trow) * KVT_ROW_B +
                                                   (n0 + jn * 16 + tcol) * 2));
            #pragma unroll
            for (int im = 0; im < 2; im++)
                #pragma unroll
                for (int jn = 0; jn < 4; jn++) {
                    mma16816h(acc[im][jn * 2 + 0], afr[im], &bfr[jn][0]);
                    mma16816h(acc[im][jn * 2 + 1], afr[im], &bfr[jn][2]);
                }
            if (wn == 0) {
                mma16816h(acc_ks[0], afr[0], b_ones);
                mma16816h(acc_ks[1], afr[1], b_ones);
            }
        }
    }

    float* kvout = g_KVpart + (size_t)blockIdx.x * (DOUT * DOUT);
    const int g = lane >> 2;
    const int t = lane & 3;
    #pragma unroll
    for (int im = 0; im < 2; im++) {
        const int r0 = m0 + im * 16 + g;
        #pragma unroll
        for (int j = 0; j < 8; j++) {
            const int col = n0 + j * 8 + t * 2;
            *(float2*)(kvout + (size_t)r0 * DOUT + col) =
                make_float2(acc[im][j][0], acc[im][j][1]);
            *(float2*)(kvout + (size_t)(r0 + 8) * DOUT + col) =
                make_float2(acc[im][j][2], acc[im][j][3]);
        }
    }
    if (wn == 0 && t == 0) {
        #pragma unroll
        for (int im = 0; im < 2; im++) {
            const int r = m0 + im * 16 + g;
            g_kspart[(size_t)blockIdx.x * DOUT + r]     = acc_ks[im][0];
            g_kspart[(size_t)blockIdx.x * DOUT + r + 8] = acc_ks[im][2];
        }
    }
}

// ============================================================================
// Reduce partials -> KV (scaled fp16 hi/lo), ksum (scaled fp16 hi/lo).
// 4 independent accumulators for MLP.
// ============================================================================
__global__ void reduce_kernel()
{
    const int i = blockIdx.x * blockDim.x + threadIdx.x;
    if (i < DOUT * DOUT) {
        float s0 = 0.0f, s1 = 0.0f, s2 = 0.0f, s3 = 0.0f;
        int b = 0;
        for (; b + 3 < NB; b += 4) {
            s0 += g_KVpart[(size_t)(b + 0) * (DOUT * DOUT) + i];
            s1 += g_KVpart[(size_t)(b + 1) * (DOUT * DOUT) + i];
            s2 += g_KVpart[(size_t)(b + 2) * (DOUT * DOUT) + i];
            s3 += g_KVpart[(size_t)(b + 3) * (DOUT * DOUT) + i];
        }
        for (; b < NB; b++) s0 += g_KVpart[(size_t)b * (DOUT * DOUT) + i];
        float s = ((s0 + s1) + (s2 + s3)) * KV_SCALE_INV;
        __half hi = __float2half_rn(s);
        g_KVhi[i] = hi;
        g_KVlo[i] = __float2half_rn(s - __half2float(hi));
    } else if (i < DOUT * DOUT + DOUT) {
        const int j = i - DOUT * DOUT;
        float s0 = 0.0f, s1 = 0.0f, s2 = 0.0f, s3 = 0.0f;
        int b = 0;
        for (; b + 3 < NB; b += 4) {
            s0 += g_kspart[(size_t)(b + 0) * DOUT + j];
            s1 += g_kspart[(size_t)(b + 1) * DOUT + j];
            s2 += g_kspart[(size_t)(b + 2) * DOUT + j];
            s3 += g_kspart[(size_t)(b + 3) * DOUT + j];
        }
        for (; b < NB; b++) s0 += g_kspart[(size_t)b * DOUT + j];
        float s = ((s0 + s1) + (s2 + s3)) * 0.125f;
        __half hi = __float2half_rn(s);
        g_kshi16[j] = hi;
        g_kslo16[j] = __float2half_rn(s - __half2float(hi));
    }
}

// ============================================================================
// Kernel C: out = elu((Q @ KV) / (Q @ ksum)) via fp16 mma.
// z computed via MMA against [ksum_hi | ksum_lo | 0...] B fragment + shuffle.
// ============================================================================
__global__ __launch_bounds__(256) void out_mma(float* __restrict__ out)
{
    extern __shared__ __align__(256) unsigned char smo[];
    const uint32_t sb = smem_u32(smo);

    const int tid  = threadIdx.x;
    const int wid  = tid >> 5;
    const int lane = tid & 31;
    const int row0 = blockIdx.x * 64;

    const int m0 = (wid & 1) * 32;
    const int n0 = (wid >> 1) * 32;

    #pragma unroll
    for (int q = 0; q < 4; q++) {
        int idx = tid + q * 256;
        int r = idx >> 4, c16 = idx & 15;
        cp16(sb + OUT_Q_OFF + r * 272 + c16 * 16,
             g_Q + (size_t)(row0 + r) * DOUT + c16 * 8);
    }
    #pragma unroll
    for (int q = 0; q < 16; q++) {
        int idx = tid + q * 256;
        int part = idx >> 11;
        int rem = idx & 2047;
        int r = rem >> 4, c16 = rem & 15;
        const __half* src = (part ? g_KVlo : g_KVhi) + r * DOUT + c16 * 8;
        cp16(sb + (part ? OUT_LO_OFF : OUT_HI_OFF) + r * 272 + c16 * 16, src);
    }
    CP_COMMIT();
    __half* kss = (__half*)(smo + OUT_KS_OFF);   // [0..127]=hi, [128..255]=lo
    if (tid < 128) kss[tid] = g_kshi16[tid];
    else           kss[tid] = g_kslo16[tid - 128];
    CP_WAIT(0);
    __syncthreads();

    float acc[2][4][4];
    #pragma unroll
    for (int i = 0; i < 2; i++)
        #pragma unroll
        for (int j = 0; j < 4; j++)
            #pragma unroll
            for (int r = 0; r < 4; r++) acc[i][j][r] = 0.0f;
    float acc_z[2][4];
    #pragma unroll
    for (int i = 0; i < 2; i++)
        #pragma unroll
        for (int r = 0; r < 4; r++) acc_z[i][r] = 0.0f;

    const int a_r = (lane & 7) + (lane & 8);
    const int a_c = ((lane >> 4) & 1) * 8;
    const int zcol = lane >> 2;       // B frag col for z
    const int zk   = (lane & 3) * 2;

    #pragma unroll
    for (int ks = 0; ks < 8; ks++) {
        const int k0 = ks * 16;
        uint32_t afr[2][4];
        #pragma unroll
        for (int im = 0; im < 2; im++)
            ldsm_x4(afr[im], sb + OUT_Q_OFF +
                    (uint32_t)((m0 + im * 16 + a_r) * 272 + (k0 + a_c) * 2));
        #pragma unroll
        for (int part = 0; part < 2; part++) {
            const uint32_t Bb = sb + (part ? OUT_LO_OFF : OUT_HI_OFF);
            uint32_t bfr[2][4];
            #pragma unroll
            for (int jn = 0; jn < 2; jn++)
                ldsm_x4_t(bfr[jn], Bb + (uint32_t)((k0 + a_r) * 272 +
                                                   (n0 + jn * 16 + a_c) * 2));
            #pragma unroll
            for (int im = 0; im < 2; im++)
                #pragma unroll
                for (int jn = 0; jn < 2; jn++) {
                    mma16816h(acc[im][jn * 2 + 0], afr[im], &bfr[jn][0]);
                    mma16816h(acc[im][jn * 2 + 1], afr[im], &bfr[jn][2]);
                }
        }
        // z MMA: B col0 = ksum_hi, col1 = ksum_lo
        uint32_t zb[2] = {0u, 0u};
        if (zcol < 2) {
            const __half* kp = kss + zcol * 128 + k0 + zk;
            zb[0] = *(const uint32_t*)(kp);
            zb[1] = *(const uint32_t*)(kp + 8);
        }
        mma16816h(acc_z[0], afr[0], zb);
        mma16816h(acc_z[1], afr[1], zb);
    }

    const int g = lane >> 2;
    const int t = lane & 3;
    #pragma unroll
    for (int im = 0; im < 2; im++) {
        float den0 = acc_z[im][0] + acc_z[im][1];
        float den1 = acc_z[im][2] + acc_z[im][3];
        den0 = __shfl_sync(0xffffffffu, den0, lane & 28);
        den1 = __shfl_sync(0xffffffffu, den1, lane & 28);
        const float z0 = 8.0f / den0;   // 64 (KV scale) * 0.125 (ks scale)
        const float z1 = 8.0f / den1;
        const int lr0 = m0 + im * 16 + g;
        const int lr1 = lr0 + 8;
        #pragma unroll
        for (int j = 0; j < 4; j++) {
            const int col = n0 + j * 8 + t * 2;
            float x0 = acc[im][j][0] * z0;
            float x1 = acc[im][j][1] * z0;
            float x2 = acc[im][j][2] * z1;
            float x3 = acc[im][j][3] * z1;
            x0 = x0 > 0.0f ? x0 : expm1f(x0);
            x1 = x1 > 0.0f ? x1 : expm1f(x1);
            x2 = x2 > 0.0f ? x2 : expm1f(x2);
            x3 = x3 > 0.0f ? x3 : expm1f(x3);
            *(float2*)(out + (size_t)(row0 + lr0) * DOUT + col) = make_float2(x0, x1);
            *(float2*)(out + (size_t)(row0 + lr1) * DOUT + col) = make_float2(x2, x3);
        }
    }
}

// ============================================================================
// Launch
// ============================================================================
extern "C" void kernel_launch(void* const* d_in, const int* in_sizes, int n_in,
                              void* d_out, int out_size)
{
    const float* h  = (const float*)d_in[0];
    const float* Wq = (const float*)d_in[1];
    const float* Wk = (const float*)d_in[2];
    const float* Wv = (const float*)d_in[3];
    float* out = (float*)d_out;

    cudaFuncSetAttribute(qkv_mma, cudaFuncAttributeMaxDynamicSharedMemorySize, SM_QKV_TOTAL);
    cudaFuncSetAttribute(out_mma, cudaFuncAttributeMaxDynamicSharedMemorySize, OUT_SM_TOTAL);

    convert_w<<<(DIN * NQKV + 255) / 256, 256>>>(Wq, Wk, Wv);

    dim3 gridA(3, NBLK_M);
    qkv_mma<<<gridA, 256, SM_QKV_TOTAL>>>(h);

    kv_mma<<<NB, 256>>>();
    reduce_kernel<<<(DOUT * DOUT + DOUT + 255) / 256, 256>>>();
    out_mma<<<NROWS / 64, 256, OUT_SM_TOTAL>>>(out);
}

// round 8
// speedup vs baseline: 4.8020x; 1.0038x over previous
#include <cuda_runtime.h>
#include <cuda_fp16.h>
#include <math.h>
#include <stdint.h>

#define NROWS 200000
#define DIN   512
#define DOUT  128
#define NQKV  384
#define BK    32
#define NCHUNKS (DIN / BK)                    // 16
#define MTILE 128
#define NBLK_M ((NROWS + MTILE - 1) / MTILE)  // 1563

#define CHUNK 352
#define SLABS (CHUNK / 32)                    // 11
#define NB    ((NROWS + CHUNK - 1) / CHUNK)   // 569
#define NB4   ((NB + 3) / 4)                  // 143

#define KV_SCALE_INV  (1.0f / 64.0f)
// ksum stored fp16 scaled by 1/8; KV scaled by 1/64 -> z_eff = 8/den

// ---- scratch (device globals; no runtime allocation) ----
__device__ __half g_Q[(size_t)NROWS * DOUT];
__device__ __half g_K[(size_t)NROWS * DOUT];
__device__ __half g_V[(size_t)NROWS * DOUT];
__device__ float g_KVpart[(size_t)NB * DOUT * DOUT];
__device__ float g_kspart[(size_t)NB * DOUT];
__device__ float g_sub[4 * (DOUT * DOUT + DOUT)];   // phase-1 partial sums
__device__ __half g_KVhi[DOUT * DOUT];   // KV * 2^-6, hi
__device__ __half g_KVlo[DOUT * DOUT];   // KV * 2^-6, lo
__device__ __half g_kshi16[DOUT];        // ksum * 2^-3, hi
__device__ __half g_kslo16[DOUT];        // ksum * 2^-3, lo

// fp16 weights, row-major [k][384]
__device__ __half g_Wh[(size_t)DIN * NQKV];

// ---- qkv smem layout ----
#define A_ROW_B   80
#define A_STAGE_B (MTILE * A_ROW_B)        // 10240
#define B_ROW_B   272
#define B_STAGE_B (BK * B_ROW_B)           // 8704
#define SM_B_OFF  (2 * A_STAGE_B)          // 20480
#define SM_QKV_TOTAL (SM_B_OFF + 2 * B_STAGE_B)  // 37888

// ---- kv smem layout ----
#define KVT_ROW_B  272
#define KVT_TILE_B (32 * KVT_ROW_B)        // 8704

// ---- out smem layout (dynamic) ----
#define OUT_Q_OFF   0
#define OUT_Q_B     (64 * 272)             // 17408
#define OUT_HI_OFF  (OUT_Q_OFF + OUT_Q_B)
#define OUT_KV_B    (128 * 272)            // 34816
#define OUT_LO_OFF  (OUT_HI_OFF + OUT_KV_B)
#define OUT_KS_OFF  (OUT_LO_OFF + OUT_KV_B)          // 256 halves: [hi|lo]
#define OUT_SM_TOTAL (OUT_KS_OFF + 256 * 2)          // 87552

static __device__ __forceinline__ uint32_t smem_u32(const void* p) {
    uint32_t a;
    asm("{ .reg .u64 t; cvta.to.shared.u64 t, %1; cvt.u32.u64 %0, t; }" : "=r"(a) : "l"(p));
    return a;
}
static __device__ __forceinline__ void cp16(uint32_t dst, const void* src) {
    asm volatile("cp.async.cg.shared.global [%0], [%1], 16;" :: "r"(dst), "l"(src) : "memory");
}
static __device__ __forceinline__ void cp16z(uint32_t dst, const void* src, int sz) {
    asm volatile("cp.async.cg.shared.global [%0], [%1], 16, %2;"
                 :: "r"(dst), "l"(src), "r"(sz) : "memory");
}
#define CP_COMMIT()  asm volatile("cp.async.commit_group;" ::: "memory")
#define CP_WAIT(N)   asm volatile("cp.async.wait_group %0;" :: "n"(N) : "memory")

static __device__ __forceinline__ void ldsm_x4(uint32_t* r, uint32_t addr) {
    asm volatile("ldmatrix.sync.aligned.m8n8.x4.shared.b16 {%0,%1,%2,%3}, [%4];"
                 : "=r"(r[0]), "=r"(r[1]), "=r"(r[2]), "=r"(r[3]) : "r"(addr));
}
static __device__ __forceinline__ void ldsm_x4_t(uint32_t* r, uint32_t addr) {
    asm volatile("ldmatrix.sync.aligned.m8n8.x4.trans.shared.b16 {%0,%1,%2,%3}, [%4];"
                 : "=r"(r[0]), "=r"(r[1]), "=r"(r[2]), "=r"(r[3]) : "r"(addr));
}
static __device__ __forceinline__ void mma16816h(float* d, const uint32_t* a,
                                                 const uint32_t* b) {
    asm volatile(
        "mma.sync.aligned.m16n8k16.row.col.f32.f16.f16.f32 "
        "{%0,%1,%2,%3}, {%4,%5,%6,%7}, {%8,%9}, {%0,%1,%2,%3};"
        : "+f"(d[0]), "+f"(d[1]), "+f"(d[2]), "+f"(d[3])
        : "r"(a[0]), "r"(a[1]), "r"(a[2]), "r"(a[3]), "r"(b[0]), "r"(b[1]));
}

__device__ __forceinline__ float elu_p1(float x) {
    return x > 0.0f ? x + 1.0f : expf(x);
}

// ============================================================================
// Kernel W: fp16 weight conversion into [k][384].
// ============================================================================
__global__ void convert_w(const float* __restrict__ Wq,
                          const float* __restrict__ Wk,
                          const float* __restrict__ Wv)
{
    int idx = blockIdx.x * 256 + threadIdx.x;
    if (idx >= DIN * NQKV) return;
    int k = idx / NQKV;
    int n = idx % NQKV;
    const float* W = (n < 128) ? Wq : (n < 256) ? Wk : Wv;
    g_Wh[idx] = __float2half_rn(W[(size_t)k * DOUT + (n & 127)]);
}

// ============================================================================
// Kernel A: [Q|K|V] = f(h @ W_which) via single-pass fp16 mma.sync.
// ============================================================================
__global__ __launch_bounds__(256, 2) void qkv_mma(const float* __restrict__ h)
{
    extern __shared__ __align__(256) unsigned char sm[];
    const uint32_t sbase = smem_u32(sm);

    const int which = blockIdx.x;
    const int row0  = blockIdx.y * MTILE;
    const int tid   = threadIdx.x;
    const int wid   = tid >> 5;
    const int lane  = tid & 31;

    const int wm = wid & 3;
    const int wn = wid >> 2;
    const int m0 = wm * 32;
    const int n0w = wn * 64;

    const int arow = tid >> 1;
    const int aseg = (tid & 1) * 16;
    int lrow = row0 + arow;
    if (lrow >= NROWS) lrow = NROWS - 1;
    const float* hrow = h + (size_t)lrow * DIN + aseg;
    const uint32_t a_sts_off = (uint32_t)(arow * A_ROW_B + aseg * 2);

    const int nbase = which * 128;

    float acc[2][8][4];
    #pragma unroll
    for (int i = 0; i < 2; i++)
        #pragma unroll
        for (int j = 0; j < 8; j++)
            #pragma unroll
            for (int r = 0; r < 4; r++) acc[i][j][r] = 0.0f;

    const int a_r = (lane & 7) + (lane & 8);
    const int a_c = ((lane >> 4) & 1) * 8;
    const int b_k = (lane & 7) + (lane & 8);
    const int b_n = ((lane >> 4) & 1) * 8;

    auto issue_B = [&](int c, int stage) {
        const size_t src_row0 = (size_t)(c * BK) * NQKV + nbase;
        uint32_t dstb = sbase + SM_B_OFF + stage * B_STAGE_B;
        #pragma unroll
        for (int it = 0; it < 2; it++) {
            int idx = tid + it * 256;
            int r = idx >> 4, c16 = idx & 15;
            cp16(dstb + r * B_ROW_B + c16 * 16,
                 g_Wh + src_row0 + (size_t)r * NQKV + c16 * 8);
        }
        CP_COMMIT();
    };
    auto sts_A = [&](int stage, const float4* v) {
        uint32_t hx[8];
        #pragma unroll
        for (int j = 0; j < 4; j++) {
            __half2 p0 = __floats2half2_rn(v[j].x, v[j].y);
            __half2 p1 = __floats2half2_rn(v[j].z, v[j].w);
            hx[2*j]   = *(uint32_t*)&p0;
            hx[2*j+1] = *(uint32_t*)&p1;
        }
        uint32_t dst = sbase + stage * A_STAGE_B + a_sts_off;
        asm volatile("st.shared.v4.b32 [%0], {%1,%2,%3,%4};" :: "r"(dst),
                     "r"(hx[0]),"r"(hx[1]),"r"(hx[2]),"r"(hx[3]));
        asm volatile("st.shared.v4.b32 [%0], {%1,%2,%3,%4};" :: "r"(dst+16),
                     "r"(hx[4]),"r"(hx[5]),"r"(hx[6]),"r"(hx[7]));
    };

    float4 v[4];
    #pragma unroll
    for (int j = 0; j < 4; j++) v[j] = *(const float4*)(hrow + 4 * j);
    issue_B(0, 0);
    sts_A(0, v);

    for (int c = 0; c < NCHUNKS; c++) {
        const int stage = c & 1;

        if (c + 1 < NCHUNKS) {
            #pragma unroll
            for (int j = 0; j < 4; j++)
                v[j] = *(const float4*)(hrow + (c + 1) * BK + 4 * j);
        }
        CP_WAIT(0);
        __syncthreads();
        if (c + 1 < NCHUNKS) issue_B(c + 1, stage ^ 1);

        const uint32_t Ab = sbase + stage * A_STAGE_B;
        const uint32_t Bb = sbase + SM_B_OFF + stage * B_STAGE_B;
        #pragma unroll
        for (int ks = 0; ks < 2; ks++) {
            const int k0 = ks * 16;
            uint32_t afr[2][4];
            #pragma unroll
            for (int im = 0; im < 2; im++)
                ldsm_x4(afr[im], Ab + (uint32_t)((m0 + im * 16 + a_r) * A_ROW_B +
                                                 (k0 + a_c) * 2));
            uint32_t bfr[4][4];
            #pragma unroll
            for (int jn = 0; jn < 4; jn++)
                ldsm_x4_t(bfr[jn], Bb + (uint32_t)((k0 + b_k) * B_ROW_B +
                                                   (n0w + jn * 16 + b_n) * 2));
            #pragma unroll
            for (int im = 0; im < 2; im++)
                #pragma unroll
                for (int jn = 0; jn < 4; jn++) {
                    mma16816h(acc[im][jn * 2 + 0], afr[im], &bfr[jn][0]);
                    mma16816h(acc[im][jn * 2 + 1], afr[im], &bfr[jn][2]);
                }
        }

        if (c + 1 < NCHUNKS) sts_A(stage ^ 1, v);
    }

    __half* Out = (which == 0) ? g_Q : (which == 1) ? g_K : g_V;
    const bool act = (which < 2);
    const int g = lane >> 2;
    const int t = lane & 3;

    #pragma unroll
    for (int im = 0; im < 2; im++) {
        const int r0 = row0 + m0 + im * 16 + g;
        const int r1 = r0 + 8;
        #pragma unroll
        for (int j = 0; j < 8; j++) {
            const int col = n0w + j * 8 + t * 2;
            float c0 = acc[im][j][0], c1 = acc[im][j][1];
            float c2 = acc[im][j][2], c3 = acc[im][j][3];
            if (act) {
                c0 = elu_p1(c0); c1 = elu_p1(c1);
                c2 = elu_p1(c2); c3 = elu_p1(c3);
            }
            if (r0 < NROWS)
                *(__half2*)(Out + (size_t)r0 * DOUT + col) = __floats2half2_rn(c0, c1);
            if (r1 < NROWS)
                *(__half2*)(Out + (size_t)r1 * DOUT + col) = __floats2half2_rn(c2, c3);
        }
    }
}

// ============================================================================
// Kernel B: partial KV = K_chunk^T @ V_chunk via fp16 mma + k_sum via MMA
// against all-ones B fragment. CHUNK=352 -> 569 blocks (wave-balanced @occ2).
// ============================================================================
__global__ __launch_bounds__(256, 2) void kv_mma()
{
    __shared__ __align__(16) unsigned char sm[2 * 2 * KVT_TILE_B];  // 34816
    const uint32_t sb = smem_u32(sm);

    const int tid  = threadIdx.x;
    const int wid  = tid >> 5;
    const int lane = tid & 31;
    const int m0 = (wid & 3) * 32;
    const int n0 = (wid >> 2) * 64;
    const int wn = wid >> 2;
    const int base = blockIdx.x * CHUNK;

    float acc[2][8][4];
    #pragma unroll
    for (int i = 0; i < 2; i++)
        #pragma unroll
        for (int j = 0; j < 8; j++)
            #pragma unroll
            for (int r = 0; r < 4; r++) acc[i][j][r] = 0.0f;
    float acc_ks[2][4];
    #pragma unroll
    for (int i = 0; i < 2; i++)
        #pragma unroll
        for (int r = 0; r < 4; r++) acc_ks[i][r] = 0.0f;

    const uint32_t b_ones[2] = {0x3C003C00u, 0x3C003C00u};

    auto issue = [&](int it, int stage) {
        #pragma unroll
        for (int q = 0; q < 4; q++) {
            int idx  = tid + q * 256;
            int tile = idx >> 9;
            int row  = (idx >> 4) & 31;
            int c16  = idx & 15;
            int grow = base + it * 32 + row;
            const __half* src = (tile ? g_V : g_K) + (size_t)grow * DOUT + c16 * 8;
            uint32_t dst = sb + stage * 2 * KVT_TILE_B + tile * KVT_TILE_B +
                           row * KVT_ROW_B + c16 * 16;
            cp16z(dst, src, (grow < NROWS) ? 16 : 0);
        }
        CP_COMMIT();
    };

    const int trow = (lane & 7) + (lane & 8);
    const int tcol = ((lane >> 4) & 1) * 8;

    issue(0, 0);

    for (int it = 0; it < SLABS; it++) {
        const int stage = it & 1;
        CP_WAIT(0);
        __syncthreads();
        if (it + 1 < SLABS) issue(it + 1, stage ^ 1);

        const uint32_t Kb = sb + stage * 2 * KVT_TILE_B;
        const uint32_t Vb = Kb + KVT_TILE_B;

        #pragma unroll
        for (int ks = 0; ks < 2; ks++) {
            const int k0 = ks * 16;
            uint32_t afr[2][4];
            #pragma unroll
            for (int im = 0; im < 2; im++) {
                uint32_t t4[4];
                ldsm_x4_t(t4, Kb + (uint32_t)((k0 + trow) * KVT_ROW_B +
                                              (m0 + im * 16 + tcol) * 2));
                afr[im][0] = t4[0]; afr[im][1] = t4[2];
                afr[im][2] = t4[1]; afr[im][3] = t4[3];
            }
            uint32_t bfr[4][4];
            #pragma unroll
            for (int jn = 0; jn < 4; jn++)
                ldsm_x4_t(bfr[jn], Vb + (uint32_t)((k0 + trow) * KVT_ROW_B +
                                                   (n0 + jn * 16 + tcol) * 2));
            #pragma unroll
            for (int im = 0; im < 2; im++)
                #pragma unroll
                for (int jn = 0; jn < 4; jn++) {
                    mma16816h(acc[im][jn * 2 + 0], afr[im], &bfr[jn][0]);
                    mma16816h(acc[im][jn * 2 + 1], afr[im], &bfr[jn][2]);
                }
            if (wn == 0) {
                mma16816h(acc_ks[0], afr[0], b_ones);
                mma16816h(acc_ks[1], afr[1], b_ones);
            }
        }
    }

    float* kvout = g_KVpart + (size_t)blockIdx.x * (DOUT * DOUT);
    const int g = lane >> 2;
    const int t = lane & 3;
    #pragma unroll
    for (int im = 0; im < 2; im++) {
        const int r0 = m0 + im * 16 + g;
        #pragma unroll
        for (int j = 0; j < 8; j++) {
            const int col = n0 + j * 8 + t * 2;
            *(float2*)(kvout + (size_t)r0 * DOUT + col) =
                make_float2(acc[im][j][0], acc[im][j][1]);
            *(float2*)(kvout + (size_t)(r0 + 8) * DOUT + col) =
                make_float2(acc[im][j][2], acc[im][j][3]);
        }
    }
    if (wn == 0 && t == 0) {
        #pragma unroll
        for (int im = 0; im < 2; im++) {
            const int r = m0 + im * 16 + g;
            g_kspart[(size_t)blockIdx.x * DOUT + r]     = acc_ks[im][0];
            g_kspart[(size_t)blockIdx.x * DOUT + r + 8] = acc_ks[im][2];
        }
    }
}

// ============================================================================
// Reduce phase 1: 4 sub-range partial sums. Grid (65, 4).
// ============================================================================
__global__ void reduce1()
{
    const int sub = blockIdx.y;
    const int i = blockIdx.x * blockDim.x + threadIdx.x;
    if (i >= DOUT * DOUT + DOUT) return;
    const int b0 = sub * NB4;
    const int b1 = (b0 + NB4 < NB) ? b0 + NB4 : NB;

    float s0 = 0.0f, s1 = 0.0f, s2 = 0.0f, s3 = 0.0f;
    if (i < DOUT * DOUT) {
        int b = b0;
        for (; b + 3 < b1; b += 4) {
            s0 += g_KVpart[(size_t)(b + 0) * (DOUT * DOUT) + i];
            s1 += g_KVpart[(size_t)(b + 1) * (DOUT * DOUT) + i];
            s2 += g_KVpart[(size_t)(b + 2) * (DOUT * DOUT) + i];
            s3 += g_KVpart[(size_t)(b + 3) * (DOUT * DOUT) + i];
        }
        for (; b < b1; b++) s0 += g_KVpart[(size_t)b * (DOUT * DOUT) + i];
    } else {
        const int j = i - DOUT * DOUT;
        int b = b0;
        for (; b + 3 < b1; b += 4) {
            s0 += g_kspart[(size_t)(b + 0) * DOUT + j];
            s1 += g_kspart[(size_t)(b + 1) * DOUT + j];
            s2 += g_kspart[(size_t)(b + 2) * DOUT + j];
            s3 += g_kspart[(size_t)(b + 3) * DOUT + j];
        }
        for (; b < b1; b++) s0 += g_kspart[(size_t)b * DOUT + j];
    }
    g_sub[sub * (DOUT * DOUT + DOUT) + i] = ((s0 + s1) + (s2 + s3));
}

// ============================================================================
// Reduce phase 2: combine 4 subs, emit fp16 hi/lo KV and ksum.
// ============================================================================
__global__ void reduce2()
{
    const int i = blockIdx.x * blockDim.x + threadIdx.x;
    if (i >= DOUT * DOUT + DOUT) return;
    const int stride = DOUT * DOUT + DOUT;
    float s = (g_sub[i] + g_sub[stride + i]) +
              (g_sub[2 * stride + i] + g_sub[3 * stride + i]);
    if (i < DOUT * DOUT) {
        s *= KV_SCALE_INV;
        __half hi = __float2half_rn(s);
        g_KVhi[i] = hi;
        g_KVlo[i] = __float2half_rn(s - __half2float(hi));
    } else {
        const int j = i - DOUT * DOUT;
        s *= 0.125f;
        __half hi = __float2half_rn(s);
        g_kshi16[j] = hi;
        g_kslo16[j] = __float2half_rn(s - __half2float(hi));
    }
}

// ============================================================================
// Kernel C: out = elu((Q @ KV) / (Q @ ksum)) via fp16 mma. occ 2.
// ============================================================================
__global__ __launch_bounds__(256, 2) void out_mma(float* __restrict__ out)
{
    extern __shared__ __align__(256) unsigned char smo[];
    const uint32_t sb = smem_u32(smo);

    const int tid  = threadIdx.x;
    const int wid  = tid >> 5;
    const int lane = tid & 31;
    const int row0 = blockIdx.x * 64;

    const int m0 = (wid & 1) * 32;
    const int n0 = (wid >> 1) * 32;

    #pragma unroll
    for (int q = 0; q < 4; q++) {
        int idx = tid + q * 256;
        int r = idx >> 4, c16 = idx & 15;
        cp16(sb + OUT_Q_OFF + r * 272 + c16 * 16,
             g_Q + (size_t)(row0 + r) * DOUT + c16 * 8);
    }
    #pragma unroll
    for (int q = 0; q < 16; q++) {
        int idx = tid + q * 256;
        int part = idx >> 11;
        int rem = idx & 2047;
        int r = rem >> 4, c16 = rem & 15;
        const __half* src = (part ? g_KVlo : g_KVhi) + r * DOUT + c16 * 8;
        cp16(sb + (part ? OUT_LO_OFF : OUT_HI_OFF) + r * 272 + c16 * 16, src);
    }
    CP_COMMIT();
    __half* kss = (__half*)(smo + OUT_KS_OFF);
    if (tid < 128) kss[tid] = g_kshi16[tid];
    else           kss[tid] = g_kslo16[tid - 128];
    CP_WAIT(0);
    __syncthreads();

    float acc[2][4][4];
    #pragma unroll
    for (int i = 0; i < 2; i++)
        #pragma unroll
        for (int j = 0; j < 4; j++)
            #pragma unroll
            for (int r = 0; r < 4; r++) acc[i][j][r] = 0.0f;
    float acc_z[2][4];
    #pragma unroll
    for (int i = 0; i < 2; i++)
        #pragma unroll
        for (int r = 0; r < 4; r++) acc_z[i][r] = 0.0f;

    const int a_r = (lane & 7) + (lane & 8);
    const int a_c = ((lane >> 4) & 1) * 8;
    const int zcol = lane >> 2;
    const int zk   = (lane & 3) * 2;

    #pragma unroll
    for (int ks = 0; ks < 8; ks++) {
        const int k0 = ks * 16;
        uint32_t afr[2][4];
        #pragma unroll
        for (int im = 0; im < 2; im++)
            ldsm_x4(afr[im], sb + OUT_Q_OFF +
                    (uint32_t)((m0 + im * 16 + a_r) * 272 + (k0 + a_c) * 2));
        #pragma unroll
        for (int part = 0; part < 2; part++) {
            const uint32_t Bb = sb + (part ? OUT_LO_OFF : OUT_HI_OFF);
            uint32_t bfr[2][4];
            #pragma unroll
            for (int jn = 0; jn < 2; jn++)
                ldsm_x4_t(bfr[jn], Bb + (uint32_t)((k0 + a_r) * 272 +
                                                   (n0 + jn * 16 + a_c) * 2));
            #pragma unroll
            for (int im = 0; im < 2; im++)
                #pragma unroll
                for (int jn = 0; jn < 2; jn++) {
                    mma16816h(acc[im][jn * 2 + 0], afr[im], &bfr[jn][0]);
                    mma16816h(acc[im][jn * 2 + 1], afr[im], &bfr[jn][2]);
                }
        }
        uint32_t zb[2] = {0u, 0u};
        if (zcol < 2) {
            const __half* kp = kss + zcol * 128 + k0 + zk;
            zb[0] = *(const uint32_t*)(kp);
            zb[1] = *(const uint32_t*)(kp + 8);
        }
        mma16816h(acc_z[0], afr[0], zb);
        mma16816h(acc_z[1], afr[1], zb);
    }

    const int g = lane >> 2;
    const int t = lane & 3;
    #pragma unroll
    for (int im = 0; im < 2; im++) {
        float den0 = acc_z[im][0] + acc_z[im][1];
        float den1 = acc_z[im][2] + acc_z[im][3];
        den0 = __shfl_sync(0xffffffffu, den0, lane & 28);
        den1 = __shfl_sync(0xffffffffu, den1, lane & 28);
        const float z0 = 8.0f / den0;
        const float z1 = 8.0f / den1;
        const int lr0 = m0 + im * 16 + g;
        const int lr1 = lr0 + 8;
        #pragma unroll
        for (int j = 0; j < 4; j++) {
            const int col = n0 + j * 8 + t * 2;
            float x0 = acc[im][j][0] * z0;
            float x1 = acc[im][j][1] * z0;
            float x2 = acc[im][j][2] * z1;
            float x3 = acc[im][j][3] * z1;
            x0 = x0 > 0.0f ? x0 : expm1f(x0);
            x1 = x1 > 0.0f ? x1 : expm1f(x1);
            x2 = x2 > 0.0f ? x2 : expm1f(x2);
            x3 = x3 > 0.0f ? x3 : expm1f(x3);
            *(float2*)(out + (size_t)(row0 + lr0) * DOUT + col) = make_float2(x0, x1);
            *(float2*)(out + (size_t)(row0 + lr1) * DOUT + col) = make_float2(x2, x3);
        }
    }
}

// ============================================================================
// Launch
// ============================================================================
extern "C" void kernel_launch(void* const* d_in, const int* in_sizes, int n_in,
                              void* d_out, int out_size)
{
    const float* h  = (const float*)d_in[0];
    const float* Wq = (const float*)d_in[1];
    const float* Wk = (const float*)d_in[2];
    const float* Wv = (const float*)d_in[3];
    float* out = (float*)d_out;

    cudaFuncSetAttribute(qkv_mma, cudaFuncAttributeMaxDynamicSharedMemorySize, SM_QKV_TOTAL);
    cudaFuncSetAttribute(out_mma, cudaFuncAttributeMaxDynamicSharedMemorySize, OUT_SM_TOTAL);

    convert_w<<<(DIN * NQKV + 255) / 256, 256>>>(Wq, Wk, Wv);

    dim3 gridA(3, NBLK_M);
    qkv_mma<<<gridA, 256, SM_QKV_TOTAL>>>(h);

    kv_mma<<<NB, 256>>>();

    dim3 gridR1((DOUT * DOUT + DOUT + 255) / 256, 4);
    reduce1<<<gridR1, 256>>>();
    reduce2<<<(DOUT * DOUT + DOUT + 255) / 256, 256>>>();

    out_mma<<<NROWS / 64, 256, OUT_SM_TOTAL>>>(out);
}